// round 14
// baseline (speedup 1.0000x reference)
#include <cuda_runtime.h>
#include <cuda_bf16.h>
#include <cstdint>

#define B_ 16
#define V_ 40000
#define C_ 128
#define H_ 56
#define W_ 56
#define E_ 120000
#define HW_ (H_*W_)
#define BV_ (B_*V_)
#define NSUM_BLKS (BV_/8)      // 80000
#define GEMM_BLKS (BV_/128)    // 5000

// ---------------- scratch (device globals; no cudaMalloc allowed) ----------------
__device__ float g_featT[B_*HW_*C_];
__device__ float g_x[BV_*C_];
__device__ float g_d[BV_*C_];
__device__ float g_t[BV_*C_];
__device__ int   g_deg[V_];
__device__ int   g_off[V_+1];
__device__ int   g_cur[V_];
__device__ int   g_adj[2*E_];
__device__ int   g_cnt[3*GEMM_BLKS];   // per-conv per-tile nsum completion counters
__device__ __nv_bfloat16 g_whi[6*128*128];
__device__ __nv_bfloat16 g_wlo[6*128*128];
__device__ __nv_bfloat16 g_xh[BV_*C_];
__device__ __nv_bfloat16 g_xl[BV_*C_];
__device__ __nv_bfloat16 g_dh[BV_*C_];
__device__ __nv_bfloat16 g_dl[BV_*C_];
__device__ __nv_bfloat16 g_sh[BV_*C_];
__device__ __nv_bfloat16 g_sl[BV_*C_];

// ================= helpers =================
__device__ __forceinline__ uint32_t smem_to_u32(const void* p){
    uint32_t a;
    asm("{ .reg .u64 t; cvta.to.shared.u64 t, %1; cvt.u32.u64 %0, t; }" : "=r"(a) : "l"(p));
    return a;
}
__device__ __forceinline__ void ldsm4(uint32_t* r, uint32_t addr){
    asm volatile("ldmatrix.sync.aligned.m8n8.x4.shared.b16 {%0,%1,%2,%3}, [%4];"
        : "=r"(r[0]), "=r"(r[1]), "=r"(r[2]), "=r"(r[3]) : "r"(addr));
}
__device__ __forceinline__ void mma_bf16(float* c, const uint32_t* a, const uint32_t* b){
    asm volatile("mma.sync.aligned.m16n8k16.row.col.f32.bf16.bf16.f32 "
        "{%0,%1,%2,%3}, {%4,%5,%6,%7}, {%8,%9}, {%0,%1,%2,%3};"
        : "+f"(c[0]), "+f"(c[1]), "+f"(c[2]), "+f"(c[3])
        : "r"(a[0]), "r"(a[1]), "r"(a[2]), "r"(a[3]), "r"(b[0]), "r"(b[1]));
}
__device__ __forceinline__ void cpasync16(uint32_t dst, const void* src){
    asm volatile("cp.async.cg.shared.global [%0], [%1], 16;" :: "r"(dst), "l"(src));
}
#define CP_COMMIT() asm volatile("cp.async.commit_group;" ::: "memory")
#define CP_WAIT0()  asm volatile("cp.async.wait_group 0;" ::: "memory")

__device__ __forceinline__ unsigned short bf_hi(float x){
    __nv_bfloat16 h = __float2bfloat16(x);
    return *(unsigned short*)&h;
}
__device__ __forceinline__ unsigned short bf_lo(float x){
    __nv_bfloat16 h = __float2bfloat16(x);
    float r = x - __bfloat162float(h);
    __nv_bfloat16 lo = __float2bfloat16(r);
    return *(unsigned short*)&lo;
}
__device__ __forceinline__ uint32_t bfpair_hi(float a, float b){
    return (uint32_t)bf_hi(a) | ((uint32_t)bf_hi(b) << 16);
}
__device__ __forceinline__ uint32_t bfpair_lo(float a, float b){
    return (uint32_t)bf_lo(a) | ((uint32_t)bf_lo(b) << 16);
}
__device__ __forceinline__ float4 bfpair4_to_f4(uint2 h, uint2 l){
    float2 a = __bfloat1622float2(*(const __nv_bfloat162*)&h.x);
    float2 b = __bfloat1622float2(*(const __nv_bfloat162*)&l.x);
    float2 c = __bfloat1622float2(*(const __nv_bfloat162*)&h.y);
    float2 d = __bfloat1622float2(*(const __nv_bfloat162*)&l.y);
    return make_float4(a.x + b.x, a.y + b.y, c.x + d.x, c.y + d.y);
}
__device__ __forceinline__ unsigned long long pack2(float lo, float hi){
    unsigned long long r;
    asm("mov.b64 %0, {%1, %2};" : "=l"(r) : "f"(lo), "f"(hi));
    return r;
}
__device__ __forceinline__ void ffma2(unsigned long long &acc, unsigned long long a, unsigned long long b){
    asm("fma.rn.f32x2 %0, %1, %2, %0;" : "+l"(acc) : "l"(a), "l"(b));
}
__device__ __forceinline__ float2 unpack2(unsigned long long v){
    float2 f;
    asm("mov.b64 {%0, %1}, %2;" : "=f"(f.x), "=f"(f.y) : "l"(v));
    return f;
}
// acquire-spin until tile's 16 nsum CTAs have signaled
__device__ __forceinline__ void wait_tile(const int* cnt){
    volatile const int* c = cnt;
    if (*c < 16){
        while (*c < 16) __nanosleep(200);
    }
    __threadfence();
}

// ---------------- 0) transpose [B,C,H,W] -> [B,H,W,C] ----------------
__global__ void transpose_kernel(const float* __restrict__ in, float* __restrict__ out){
    __shared__ float tile[32][33];
    int b = blockIdx.z;
    int hw0 = blockIdx.x*32, c0 = blockIdx.y*32;
    int tx = threadIdx.x, ty = threadIdx.y;
    #pragma unroll
    for (int k=0;k<4;k++){
        int c = c0 + ty + k*8;
        tile[ty+k*8][tx] = in[((size_t)(b*C_ + c))*HW_ + hw0 + tx];
    }
    __syncthreads();
    #pragma unroll
    for (int k=0;k<4;k++){
        int hw = hw0 + ty + k*8;
        out[((size_t)b*HW_ + hw)*C_ + c0 + tx] = tile[tx][ty+k*8];
    }
}

// ---------------- 1) vert_align + vertex_padded -> g_x (+ hi/lo split) ----------------
__global__ __launch_bounds__(256) void valign_kernel(
    const float* __restrict__ featT, const float* __restrict__ vpos,
    const float* __restrict__ vpad, float* __restrict__ g,
    __nv_bfloat16* __restrict__ gh, __nv_bfloat16* __restrict__ gl)
{
    int warp = blockIdx.x * 8 + (threadIdx.x >> 5);
    if (warp >= BV_) return;
    int lane = threadIdx.x & 31;
    int b = warp / V_;

    const float* vp = vpos + (size_t)warp*3;
    float fx = (vp[0] + 1.f) * 0.5f * (float)(W_-1);
    float fy = (vp[1] + 1.f) * 0.5f * (float)(H_-1);
    float x0f = floorf(fx), y0f = floorf(fy);
    float wx1 = fx - x0f, wx0 = 1.f - wx1;
    float wy1 = fy - y0f, wy0 = 1.f - wy1;
    int x0 = (int)x0f, y0 = (int)y0f;

    const float4* fb = (const float4*)featT + (size_t)b*HW_*32;
    float4 acc = make_float4(0.f,0.f,0.f,0.f);

    int xs[4] = {x0, x0+1, x0,   x0+1};
    int ys[4] = {y0, y0,   y0+1, y0+1};
    float wt[4] = {wx0*wy0, wx1*wy0, wx0*wy1, wx1*wy1};
    #pragma unroll
    for (int t=0;t<4;t++){
        int xi = xs[t], yi = ys[t];
        if (xi >= 0 && xi < W_ && yi >= 0 && yi < H_){
            float4 f = fb[(size_t)(yi*W_+xi)*32 + lane];
            float w = wt[t];
            acc.x += w*f.x; acc.y += w*f.y; acc.z += w*f.z; acc.w += w*f.w;
        }
    }
    float4 pv = ((const float4*)vpad)[(size_t)warp*32 + lane];
    acc.x += pv.x; acc.y += pv.y; acc.z += pv.z; acc.w += pv.w;
    ((float4*)g)[(size_t)warp*32 + lane] = acc;
    size_t off = (size_t)warp*128 + lane*4;
    *(uint2*)(gh + off) = make_uint2(bfpair_hi(acc.x, acc.y), bfpair_hi(acc.z, acc.w));
    *(uint2*)(gl + off) = make_uint2(bfpair_lo(acc.x, acc.y), bfpair_lo(acc.z, acc.w));
}

// ---------------- 2) CSR build + counter zeroing ----------------
__global__ void zero_aux_kernel(){
    int i = blockIdx.x*256 + threadIdx.x;
    if (i < V_) g_deg[i] = 0;
    if (i < 3*GEMM_BLKS) g_cnt[i] = 0;
}
__global__ void count_deg_kernel(const int* __restrict__ edges){
    int e = blockIdx.x*256 + threadIdx.x;
    if (e < E_){
        int i = edges[2*e], j = edges[2*e+1];
        atomicAdd(&g_deg[i], 1);
        atomicAdd(&g_deg[j], 1);
    }
}
__global__ void scan_kernel(){
    __shared__ int wsum[32];
    __shared__ int s_carry;
    if (threadIdx.x == 0) s_carry = 0;
    __syncthreads();
    int lane = threadIdx.x & 31, w = threadIdx.x >> 5;
    for (int base = 0; base < V_; base += 1024){
        int i = base + (int)threadIdx.x;
        int v = (i < V_) ? g_deg[i] : 0;
        int x = v;
        #pragma unroll
        for (int d=1; d<32; d<<=1){ int y=__shfl_up_sync(0xffffffffu, x, d); if (lane>=d) x+=y; }
        if (lane == 31) wsum[w] = x;
        __syncthreads();
        if (w == 0){
            int s = wsum[lane];
            #pragma unroll
            for (int d=1; d<32; d<<=1){ int y=__shfl_up_sync(0xffffffffu, s, d); if (lane>=d) s+=y; }
            wsum[lane] = s;
        }
        __syncthreads();
        int incl = x + (w ? wsum[w-1] : 0) + s_carry;
        if (i < V_){ int ex = incl - v; g_off[i] = ex; g_cur[i] = ex; }
        __syncthreads();
        if (threadIdx.x == 1023) s_carry = incl;
        __syncthreads();
    }
    if (threadIdx.x == 0) g_off[V_] = s_carry;
}
__global__ void fill_adj_kernel(const int* __restrict__ edges){
    int e = blockIdx.x*256 + threadIdx.x;
    if (e < E_){
        int i = edges[2*e], j = edges[2*e+1];
        int p = atomicAdd(&g_cur[i], 1); g_adj[p] = j;
        int q = atomicAdd(&g_cur[j], 1); g_adj[q] = i;
    }
}

// ---------------- 3) weight transpose + bf16 split (all 6 in one launch) ----------------
__global__ void wsplit_all_kernel(const float* __restrict__ w0, const float* __restrict__ w1,
                                  const float* __restrict__ w2, const float* __restrict__ w3,
                                  const float* __restrict__ w4, const float* __restrict__ w5,
                                  __nv_bfloat16* __restrict__ hi, __nv_bfloat16* __restrict__ lo){
    int m = blockIdx.x >> 6;
    const float* w = (m==0)?w0:(m==1)?w1:(m==2)?w2:(m==3)?w3:(m==4)?w4:w5;
    int idx = (blockIdx.x & 63)*256 + threadIdx.x;
    int n = idx & 127, k = idx >> 7;
    float v = w[k*128 + n];
    __nv_bfloat16 h = __float2bfloat16(v);
    hi[m*16384 + n*128 + k] = h;
    lo[m*16384 + n*128 + k] = __float2bfloat16(v - __bfloat162float(h));
}

// ================= 4) FUSED nsum + HYBRID dual-pipe GEMM (one launch per conv) =================
// bids [0, NSUM_BLKS): nsum role — gather fp32 X, emit Sh/Sl, signal per-tile counter.
// bids [NSUM_BLKS, +GEMM_BLKS): GEMM role — X passes immediately; acquire-spin on the
// tile counter just before the S passes. H/F typing and schedules as R13.
#define TS_A0 0
#define TS_A1 32768
#define TS_B  65536
#define TSMEM 98304

__global__ __launch_bounds__(256, 2) void fused_conv_kernel(
    const float* __restrict__ X,
    const __nv_bfloat16* __restrict__ Xh, const __nv_bfloat16* __restrict__ Xl,
    __nv_bfloat16* __restrict__ Shw, __nv_bfloat16* __restrict__ Slw,   // nsum outputs (write)
    const float* __restrict__ Wa32, const float* __restrict__ Wb32,
    const __nv_bfloat16* __restrict__ Whi, const __nv_bfloat16* __restrict__ Wlo,
    const float* __restrict__ bias, const float* __restrict__ Z,
    float* __restrict__ Y,
    __nv_bfloat16* __restrict__ Yh, __nv_bfloat16* __restrict__ Yl,
    int* __restrict__ cnt)
{
    extern __shared__ char smem[];
    const int tid = threadIdx.x;

    if (blockIdx.x < NSUM_BLKS){
        // ======== nsum role ========
        int warp = blockIdx.x * 8 + (tid >> 5);
        int lane = tid & 31;
        int b = warp / V_, i = warp - b*V_;
        const float4* xb = (const float4*)(X + (size_t)b*V_*C_);
        float4 acc = make_float4(0.f,0.f,0.f,0.f);
        int p0 = g_off[i], p1 = g_off[i+1];
        for (int p = p0; p < p1; p++){
            int j = g_adj[p];
            float4 v = xb[(size_t)j*32 + lane];
            acc.x += v.x; acc.y += v.y; acc.z += v.z; acc.w += v.w;
        }
        size_t off = (size_t)warp*128 + lane*4;
        *(uint2*)(Shw + off) = make_uint2(bfpair_hi(acc.x, acc.y), bfpair_hi(acc.z, acc.w));
        *(uint2*)(Slw + off) = make_uint2(bfpair_lo(acc.x, acc.y), bfpair_lo(acc.z, acc.w));
        __threadfence();
        __syncthreads();
        if (tid == 0) atomicAdd(&cnt[blockIdx.x >> 4], 1);
        return;
    }

    const int tile = blockIdx.x - NSUM_BLKS;
    const long row0 = (long)tile * 128;
    const bool useH = (tile & 7) < 4;
    const int* mycnt = cnt + tile;
    const __nv_bfloat16* Sh = Shw;
    const __nv_bfloat16* Sl = Slw;

    if (useH){
        // ======== tensor-pipe path: pipelined load-only bf16x3 ========
        uint32_t sbase = smem_to_u32(smem);
        const int l = tid & 31;
        const int wid = tid >> 5;
        const int warp_m = wid >> 2;
        const int warp_n = wid & 3;

        float acc[4][4][4];
        #pragma unroll
        for (int a=0;a<4;a++)
            #pragma unroll
            for (int b=0;b<4;b++)
                #pragma unroll
                for (int c=0;c<4;c++) acc[a][b][c] = 0.f;

        auto loadT = [&](uint32_t dst, const __nv_bfloat16* src){
            #pragma unroll
            for (int i = 0; i < 8; i++){
                int idx = tid + i*256;
                int row = idx >> 4, c = idx & 15;
                uint32_t off = (uint32_t)(row*256 + ((c ^ ((row & 7)*2)) * 16));
                cpasync16(dst + off, src + (size_t)row*128 + c*8);
            }
        };
        auto mmapass = [&](uint32_t abuf, uint32_t bbuf){
            const int sx = (l & 7) * 2;
            uint32_t a_base = sbase + abuf + (uint32_t)((warp_m*64 + (l & 15)) * 256);
            const int a_choff = (l >> 4);
            uint32_t b_base = sbase + bbuf + (uint32_t)((warp_n*32 + ((l >> 4) << 3) + (l & 7)) * 256);
            const int b_choff = (l >> 3) & 1;
            #pragma unroll
            for (int ks = 0; ks < 8; ks++){
                uint32_t afr[4][4];
                #pragma unroll
                for (int mt = 0; mt < 4; mt++)
                    ldsm4(afr[mt], a_base + mt*4096 + (uint32_t)(((2*ks + a_choff) ^ sx) * 16));
                uint32_t bfr[2][4];
                #pragma unroll
                for (int np = 0; np < 2; np++)
                    ldsm4(bfr[np], b_base + np*4096 + (uint32_t)(((2*ks + b_choff) ^ sx) * 16));
                #pragma unroll
                for (int mt = 0; mt < 4; mt++){
                    #pragma unroll
                    for (int np = 0; np < 2; np++){
                        mma_bf16(acc[mt][2*np],   afr[mt], &bfr[np][0]);
                        mma_bf16(acc[mt][2*np+1], afr[mt], &bfr[np][2]);
                    }
                }
            }
        };

        // ---- pipelined schedule ----
        loadT(sbase + TS_B,  Whi);
        loadT(sbase + TS_A0, Xh + row0*128);
        loadT(sbase + TS_A1, Xl + row0*128);
        CP_COMMIT(); CP_WAIT0(); __syncthreads();

        mmapass(TS_A1, TS_B);                      // Xl*W0h
        __syncthreads();
        loadT(sbase + TS_A1, Wlo); CP_COMMIT();    // W0l -> A1
        mmapass(TS_A0, TS_B);                      // Xh*W0h
        CP_WAIT0(); __syncthreads();

        wait_tile(mycnt);                          // S must be ready before issuing its load
        loadT(sbase + TS_B, Sh + row0*128); CP_COMMIT();  // Sh -> B
        mmapass(TS_A0, TS_A1);                     // Xh*W0l
        CP_WAIT0(); __syncthreads();

        loadT(sbase + TS_A0, Sl + row0*128);
        loadT(sbase + TS_A1, Whi + 16384);
        CP_COMMIT(); CP_WAIT0(); __syncthreads();

        mmapass(TS_A0, TS_A1);                     // Sl*W1h
        __syncthreads();
        loadT(sbase + TS_A0, Wlo + 16384); CP_COMMIT();
        mmapass(TS_B, TS_A1);                      // Sh*W1h
        CP_WAIT0(); __syncthreads();

        mmapass(TS_B, TS_A0);                      // Sh*W1l

        // epilogue
        #pragma unroll
        for (int mt = 0; mt < 4; mt++){
            long rg = row0 + warp_m*64 + mt*16 + (l >> 2);
            #pragma unroll
            for (int nt = 0; nt < 4; nt++){
                int col = warp_n*32 + nt*8 + (l & 3)*2;
                float2 bv = *(const float2*)(bias + col);
                float2 v0 = make_float2(acc[mt][nt][0] + bv.x, acc[mt][nt][1] + bv.y);
                float2 v1 = make_float2(acc[mt][nt][2] + bv.x, acc[mt][nt][3] + bv.y);
                if (Z){
                    float2 z0 = *(const float2*)(Z + rg*128 + col);
                    float2 z1 = *(const float2*)(Z + (rg+8)*128 + col);
                    v0.x += z0.x; v0.y += z0.y;
                    v1.x += z1.x; v1.y += z1.y;
                }
                *(float2*)(Y + rg*128 + col)     = v0;
                *(float2*)(Y + (rg+8)*128 + col) = v1;
                if (Yh){
                    *(uint32_t*)(Yh + rg*128 + col)     = bfpair_hi(v0.x, v0.y);
                    *(uint32_t*)(Yl + rg*128 + col)     = bfpair_lo(v0.x, v0.y);
                    *(uint32_t*)(Yh + (rg+8)*128 + col) = bfpair_hi(v1.x, v1.y);
                    *(uint32_t*)(Yl + (rg+8)*128 + col) = bfpair_lo(v1.x, v1.y);
                }
            }
        }
    } else {
        // ======== FP32 pipe path ========
        float* sx = (float*)smem;            // [2][16][132]
        float* sw = sx + 2*16*132;           // [2][16][128]
        const int tr = (tid >> 4) * 4;
        const int tc = (tid & 15) * 4;

        unsigned long long acc[8][4];
        #pragma unroll
        for (int r=0;r<8;r++)
            #pragma unroll
            for (int c=0;c<4;c++) acc[r][c] = 0ull;

        float4 rx0, rx1, rw0, rw1;

        auto fetch = [&](int s){
            const float* Wm = (s < 8) ? Wa32 : Wb32;
            const int kx = (s & 7) * 16;
            {
                int idx = tid;
                int row = idx >> 2, q = idx & 3;
                size_t o = (size_t)(row0+row)*128 + kx + q*4;
                if (s < 8){
                    rx0 = *(const float4*)(X + o);
                } else {
                    uint2 h2 = *(const uint2*)(Sh + o);
                    uint2 l2 = *(const uint2*)(Sl + o);
                    rx0 = bfpair4_to_f4(h2, l2);
                }
                int kr = idx >> 5, cq = idx & 31;
                rw0 = *(const float4*)(Wm + (size_t)(kx+kr)*128 + cq*4);
            }
            {
                int idx = tid + 256;
                int row = idx >> 2, q = idx & 3;
                size_t o = (size_t)(row0+row)*128 + kx + q*4;
                if (s < 8){
                    rx1 = *(const float4*)(X + o);
                } else {
                    uint2 h2 = *(const uint2*)(Sh + o);
                    uint2 l2 = *(const uint2*)(Sl + o);
                    rx1 = bfpair4_to_f4(h2, l2);
                }
                int kr = idx >> 5, cq = idx & 31;
                rw1 = *(const float4*)(Wm + (size_t)(kx+kr)*128 + cq*4);
            }
        };
        auto store = [&](int buf){
            float* xb = sx + buf*2112;
            float* wb = sw + buf*2048;
            {
                int idx = tid;
                int row = idx >> 2, q = idx & 3;
                xb[(q*4+0)*132+row] = rx0.x; xb[(q*4+1)*132+row] = rx0.y;
                xb[(q*4+2)*132+row] = rx0.z; xb[(q*4+3)*132+row] = rx0.w;
                int kr = idx >> 5, cq = idx & 31;
                *(float4*)&wb[kr*128 + cq*4] = rw0;
            }
            {
                int idx = tid + 256;
                int row = idx >> 2, q = idx & 3;
                xb[(q*4+0)*132+row] = rx1.x; xb[(q*4+1)*132+row] = rx1.y;
                xb[(q*4+2)*132+row] = rx1.z; xb[(q*4+3)*132+row] = rx1.w;
                int kr = idx >> 5, cq = idx & 31;
                *(float4*)&wb[kr*128 + cq*4] = rw1;
            }
        };

        fetch(0); store(0);
        __syncthreads();

        #pragma unroll 1
        for (int s = 0; s < 16; s++){
            int buf = s & 1;
            float* xb = sx + buf*2112;
            float* wb = sw + buf*2048;
            if (s == 7) wait_tile(mycnt);    // S pass starts at s=8 (prefetched here)
            if (s < 15) fetch(s+1);
            #pragma unroll
            for (int k = 0; k < 16; k++){
                float4 xa = *(const float4*)&xb[k*132 + tr];
                float4 xc = *(const float4*)&xb[k*132 + tr+64];
                float4 wa = *(const float4*)&wb[k*128 + tc];
                float4 wc = *(const float4*)&wb[k*128 + tc+64];
                unsigned long long wp0 = pack2(wa.x, wa.y);
                unsigned long long wp1 = pack2(wa.z, wa.w);
                unsigned long long wp2 = pack2(wc.x, wc.y);
                unsigned long long wp3 = pack2(wc.z, wc.w);
                float xr[8] = {xa.x,xa.y,xa.z,xa.w, xc.x,xc.y,xc.z,xc.w};
                #pragma unroll
                for (int r=0;r<8;r++){
                    unsigned long long ad = pack2(xr[r], xr[r]);
                    ffma2(acc[r][0], ad, wp0);
                    ffma2(acc[r][1], ad, wp1);
                    ffma2(acc[r][2], ad, wp2);
                    ffma2(acc[r][3], ad, wp3);
                }
            }
            if (s < 15) store((s+1)&1);
            __syncthreads();
        }

        float4 ba = *(const float4*)(bias + tc);
        float4 bb = *(const float4*)(bias + tc + 64);
        #pragma unroll
        for (int r=0;r<8;r++){
            long row = row0 + tr + (r & 3) + ((r >> 2) * 64);
            float2 p0 = unpack2(acc[r][0]), p1 = unpack2(acc[r][1]);
            float2 p2 = unpack2(acc[r][2]), p3 = unpack2(acc[r][3]);
            float4 v0 = make_float4(p0.x + ba.x, p0.y + ba.y, p1.x + ba.z, p1.y + ba.w);
            float4 v1 = make_float4(p2.x + bb.x, p2.y + bb.y, p3.x + bb.z, p3.y + bb.w);
            if (Z){
                float4 z0 = *(const float4*)(Z + row*128 + tc);
                float4 z1 = *(const float4*)(Z + row*128 + tc + 64);
                v0.x += z0.x; v0.y += z0.y; v0.z += z0.z; v0.w += z0.w;
                v1.x += z1.x; v1.y += z1.y; v1.z += z1.z; v1.w += z1.w;
            }
            *(float4*)(Y + row*128 + tc)      = v0;
            *(float4*)(Y + row*128 + tc + 64) = v1;
            if (Yh){
                *(uint2*)(Yh + row*128 + tc)      = make_uint2(bfpair_hi(v0.x,v0.y), bfpair_hi(v0.z,v0.w));
                *(uint2*)(Yl + row*128 + tc)      = make_uint2(bfpair_lo(v0.x,v0.y), bfpair_lo(v0.z,v0.w));
                *(uint2*)(Yh + row*128 + tc + 64) = make_uint2(bfpair_hi(v1.x,v1.y), bfpair_hi(v1.z,v1.w));
                *(uint2*)(Yl + row*128 + tc + 64) = make_uint2(bfpair_lo(v1.x,v1.y), bfpair_lo(v1.z,v1.w));
            }
        }
    }
}

// ---------------- launch ----------------
extern "C" void kernel_launch(void* const* d_in, const int* in_sizes, int n_in,
                              void* d_out, int out_size)
{
    const float* img  = (const float*)d_in[0];
    const float* vpos = (const float*)d_in[1];
    const float* vpad = (const float*)d_in[2];
    const int*   edges= (const int*)  d_in[3];
    const float* w0_1 = (const float*)d_in[4];
    const float* b0_1 = (const float*)d_in[5];
    const float* w1_1 = (const float*)d_in[6];
    const float* w0_2 = (const float*)d_in[7];
    const float* b0_2 = (const float*)d_in[8];
    const float* w1_2 = (const float*)d_in[9];
    const float* w0_3 = (const float*)d_in[10];
    const float* b0_3 = (const float*)d_in[11];
    const float* w1_3 = (const float*)d_in[12];
    float* out = (float*)d_out;

    float *pft, *px, *pd, *pt;
    int *pcnt;
    __nv_bfloat16 *pwh, *pwl, *pxh, *pxl, *pdh, *pdl, *psh, *psl;
    cudaGetSymbolAddress((void**)&pft, g_featT);
    cudaGetSymbolAddress((void**)&px,  g_x);
    cudaGetSymbolAddress((void**)&pd,  g_d);
    cudaGetSymbolAddress((void**)&pt,  g_t);
    cudaGetSymbolAddress((void**)&pcnt, g_cnt);
    cudaGetSymbolAddress((void**)&pwh, g_whi);
    cudaGetSymbolAddress((void**)&pwl, g_wlo);
    cudaGetSymbolAddress((void**)&pxh, g_xh);
    cudaGetSymbolAddress((void**)&pxl, g_xl);
    cudaGetSymbolAddress((void**)&pdh, g_dh);
    cudaGetSymbolAddress((void**)&pdl, g_dl);
    cudaGetSymbolAddress((void**)&psh, g_sh);
    cudaGetSymbolAddress((void**)&psl, g_sl);

    cudaFuncSetAttribute(fused_conv_kernel, cudaFuncAttributeMaxDynamicSharedMemorySize, TSMEM);

    transpose_kernel<<<dim3(HW_/32, C_/32, B_), dim3(32,8)>>>(img, pft);
    valign_kernel<<<BV_/8, 256>>>(pft, vpos, vpad, px, pxh, pxl);
    zero_aux_kernel<<<(V_+255)/256, 256>>>();
    count_deg_kernel<<<(E_+255)/256, 256>>>(edges);
    scan_kernel<<<1, 1024>>>();
    fill_adj_kernel<<<(E_+255)/256, 256>>>(edges);
    wsplit_all_kernel<<<384, 256>>>(w0_1, w1_1, w0_2, w1_2, w0_3, w1_3, pwh, pwl);

    const int FGRID = NSUM_BLKS + GEMM_BLKS;
    // conv1: nsum(g) + [d = g@W0_1 + b0_1 + S@W1_1] ; emits fp32 d + (dh,dl)
    fused_conv_kernel<<<FGRID, 256, TSMEM>>>(px, pxh, pxl, psh, psl,
        w0_1, w1_1, pwh + 0*16384, pwl + 0*16384, b0_1, nullptr, pd, pdh, pdl,
        pcnt + 0*GEMM_BLKS);
    // conv2: nsum(d) + [t = d@W0_2 + b0_2 + S@W1_2] ; emits fp32 t + (xh,xl)
    fused_conv_kernel<<<FGRID, 256, TSMEM>>>(pd, pdh, pdl, psh, psl,
        w0_2, w1_2, pwh + 2*16384, pwl + 2*16384, b0_2, nullptr, pt, pxh, pxl,
        pcnt + 1*GEMM_BLKS);
    // conv3: nsum(t) + [out = t@W0_3 + b0_3 + S@W1_3 + d]
    fused_conv_kernel<<<FGRID, 256, TSMEM>>>(pt, pxh, pxl, psh, psl,
        w0_3, w1_3, pwh + 4*16384, pwl + 4*16384, b0_3, pd, out, nullptr, nullptr,
        pcnt + 2*GEMM_BLKS);
}

// round 15
// speedup vs baseline: 1.3011x; 1.3011x over previous
#include <cuda_runtime.h>
#include <cuda_bf16.h>
#include <cstdint>

#define B_ 16
#define V_ 40000
#define C_ 128
#define H_ 56
#define W_ 56
#define E_ 120000
#define HW_ (H_*W_)
#define BV_ (B_*V_)
#define GEMM_TILES (BV_/128)   // 5000
#define HTILES (GEMM_TILES/2)  // 2500 per type
#define PCTAS 296              // one full wave, 2 CTAs/SM

// ---------------- scratch (device globals; no cudaMalloc allowed) ----------------
__device__ float g_featT[B_*HW_*C_];
__device__ float g_x[BV_*C_];
__device__ float g_d[BV_*C_];
__device__ float g_t[BV_*C_];
__device__ int   g_deg[V_];
__device__ int   g_off[V_+1];
__device__ int   g_cur[V_];
__device__ int   g_adj[2*E_];
__device__ __nv_bfloat16 g_whi[6*128*128];
__device__ __nv_bfloat16 g_wlo[6*128*128];
__device__ __nv_bfloat16 g_xh[BV_*C_];
__device__ __nv_bfloat16 g_xl[BV_*C_];
__device__ __nv_bfloat16 g_dh[BV_*C_];
__device__ __nv_bfloat16 g_dl[BV_*C_];
__device__ __nv_bfloat16 g_sh[BV_*C_];
__device__ __nv_bfloat16 g_sl[BV_*C_];

// ================= helpers =================
__device__ __forceinline__ uint32_t smem_to_u32(const void* p){
    uint32_t a;
    asm("{ .reg .u64 t; cvta.to.shared.u64 t, %1; cvt.u32.u64 %0, t; }" : "=r"(a) : "l"(p));
    return a;
}
__device__ __forceinline__ void ldsm4(uint32_t* r, uint32_t addr){
    asm volatile("ldmatrix.sync.aligned.m8n8.x4.shared.b16 {%0,%1,%2,%3}, [%4];"
        : "=r"(r[0]), "=r"(r[1]), "=r"(r[2]), "=r"(r[3]) : "r"(addr));
}
__device__ __forceinline__ void mma_bf16(float* c, const uint32_t* a, const uint32_t* b){
    asm volatile("mma.sync.aligned.m16n8k16.row.col.f32.bf16.bf16.f32 "
        "{%0,%1,%2,%3}, {%4,%5,%6,%7}, {%8,%9}, {%0,%1,%2,%3};"
        : "+f"(c[0]), "+f"(c[1]), "+f"(c[2]), "+f"(c[3])
        : "r"(a[0]), "r"(a[1]), "r"(a[2]), "r"(a[3]), "r"(b[0]), "r"(b[1]));
}
__device__ __forceinline__ void cpasync16(uint32_t dst, const void* src){
    asm volatile("cp.async.cg.shared.global [%0], [%1], 16;" :: "r"(dst), "l"(src));
}
#define CP_COMMIT() asm volatile("cp.async.commit_group;" ::: "memory")
#define CP_WAIT0()  asm volatile("cp.async.wait_group 0;" ::: "memory")

__device__ __forceinline__ unsigned short bf_hi(float x){
    __nv_bfloat16 h = __float2bfloat16(x);
    return *(unsigned short*)&h;
}
__device__ __forceinline__ unsigned short bf_lo(float x){
    __nv_bfloat16 h = __float2bfloat16(x);
    float r = x - __bfloat162float(h);
    __nv_bfloat16 lo = __float2bfloat16(r);
    return *(unsigned short*)&lo;
}
__device__ __forceinline__ uint32_t bfpair_hi(float a, float b){
    return (uint32_t)bf_hi(a) | ((uint32_t)bf_hi(b) << 16);
}
__device__ __forceinline__ uint32_t bfpair_lo(float a, float b){
    return (uint32_t)bf_lo(a) | ((uint32_t)bf_lo(b) << 16);
}
__device__ __forceinline__ float4 bfpair4_to_f4(uint2 h, uint2 l){
    float2 a = __bfloat1622float2(*(const __nv_bfloat162*)&h.x);
    float2 b = __bfloat1622float2(*(const __nv_bfloat162*)&l.x);
    float2 c = __bfloat1622float2(*(const __nv_bfloat162*)&h.y);
    float2 d = __bfloat1622float2(*(const __nv_bfloat162*)&l.y);
    return make_float4(a.x + b.x, a.y + b.y, c.x + d.x, c.y + d.y);
}
__device__ __forceinline__ unsigned long long pack2(float lo, float hi){
    unsigned long long r;
    asm("mov.b64 %0, {%1, %2};" : "=l"(r) : "f"(lo), "f"(hi));
    return r;
}
__device__ __forceinline__ void ffma2(unsigned long long &acc, unsigned long long a, unsigned long long b){
    asm("fma.rn.f32x2 %0, %1, %2, %0;" : "+l"(acc) : "l"(a), "l"(b));
}
__device__ __forceinline__ float2 unpack2(unsigned long long v){
    float2 f;
    asm("mov.b64 {%0, %1}, %2;" : "=f"(f.x), "=f"(f.y) : "l"(v));
    return f;
}

// ---------------- 0) transpose [B,C,H,W] -> [B,H,W,C] ----------------
__global__ void transpose_kernel(const float* __restrict__ in, float* __restrict__ out){
    __shared__ float tile[32][33];
    int b = blockIdx.z;
    int hw0 = blockIdx.x*32, c0 = blockIdx.y*32;
    int tx = threadIdx.x, ty = threadIdx.y;
    #pragma unroll
    for (int k=0;k<4;k++){
        int c = c0 + ty + k*8;
        tile[ty+k*8][tx] = in[((size_t)(b*C_ + c))*HW_ + hw0 + tx];
    }
    __syncthreads();
    #pragma unroll
    for (int k=0;k<4;k++){
        int hw = hw0 + ty + k*8;
        out[((size_t)b*HW_ + hw)*C_ + c0 + tx] = tile[tx][ty+k*8];
    }
}

// ---------------- 1) vert_align + vertex_padded -> g_x (+ hi/lo split) ----------------
__global__ __launch_bounds__(256) void valign_kernel(
    const float* __restrict__ featT, const float* __restrict__ vpos,
    const float* __restrict__ vpad, float* __restrict__ g,
    __nv_bfloat16* __restrict__ gh, __nv_bfloat16* __restrict__ gl)
{
    int warp = blockIdx.x * 8 + (threadIdx.x >> 5);
    if (warp >= BV_) return;
    int lane = threadIdx.x & 31;
    int b = warp / V_;

    const float* vp = vpos + (size_t)warp*3;
    float fx = (vp[0] + 1.f) * 0.5f * (float)(W_-1);
    float fy = (vp[1] + 1.f) * 0.5f * (float)(H_-1);
    float x0f = floorf(fx), y0f = floorf(fy);
    float wx1 = fx - x0f, wx0 = 1.f - wx1;
    float wy1 = fy - y0f, wy0 = 1.f - wy1;
    int x0 = (int)x0f, y0 = (int)y0f;

    const float4* fb = (const float4*)featT + (size_t)b*HW_*32;
    float4 acc = make_float4(0.f,0.f,0.f,0.f);

    int xs[4] = {x0, x0+1, x0,   x0+1};
    int ys[4] = {y0, y0,   y0+1, y0+1};
    float wt[4] = {wx0*wy0, wx1*wy0, wx0*wy1, wx1*wy1};
    #pragma unroll
    for (int t=0;t<4;t++){
        int xi = xs[t], yi = ys[t];
        if (xi >= 0 && xi < W_ && yi >= 0 && yi < H_){
            float4 f = fb[(size_t)(yi*W_+xi)*32 + lane];
            float w = wt[t];
            acc.x += w*f.x; acc.y += w*f.y; acc.z += w*f.z; acc.w += w*f.w;
        }
    }
    float4 pv = ((const float4*)vpad)[(size_t)warp*32 + lane];
    acc.x += pv.x; acc.y += pv.y; acc.z += pv.z; acc.w += pv.w;
    ((float4*)g)[(size_t)warp*32 + lane] = acc;
    size_t off = (size_t)warp*128 + lane*4;
    *(uint2*)(gh + off) = make_uint2(bfpair_hi(acc.x, acc.y), bfpair_hi(acc.z, acc.w));
    *(uint2*)(gl + off) = make_uint2(bfpair_lo(acc.x, acc.y), bfpair_lo(acc.z, acc.w));
}

// ---------------- 2) CSR build ----------------
__global__ void zero_deg_kernel(){
    int i = blockIdx.x*256 + threadIdx.x;
    if (i < V_) g_deg[i] = 0;
}
__global__ void count_deg_kernel(const int* __restrict__ edges){
    int e = blockIdx.x*256 + threadIdx.x;
    if (e < E_){
        int i = edges[2*e], j = edges[2*e+1];
        atomicAdd(&g_deg[i], 1);
        atomicAdd(&g_deg[j], 1);
    }
}
__global__ void scan_kernel(){
    __shared__ int wsum[32];
    __shared__ int s_carry;
    if (threadIdx.x == 0) s_carry = 0;
    __syncthreads();
    int lane = threadIdx.x & 31, w = threadIdx.x >> 5;
    for (int base = 0; base < V_; base += 1024){
        int i = base + (int)threadIdx.x;
        int v = (i < V_) ? g_deg[i] : 0;
        int x = v;
        #pragma unroll
        for (int d=1; d<32; d<<=1){ int y=__shfl_up_sync(0xffffffffu, x, d); if (lane>=d) x+=y; }
        if (lane == 31) wsum[w] = x;
        __syncthreads();
        if (w == 0){
            int s = wsum[lane];
            #pragma unroll
            for (int d=1; d<32; d<<=1){ int y=__shfl_up_sync(0xffffffffu, s, d); if (lane>=d) s+=y; }
            wsum[lane] = s;
        }
        __syncthreads();
        int incl = x + (w ? wsum[w-1] : 0) + s_carry;
        if (i < V_){ int ex = incl - v; g_off[i] = ex; g_cur[i] = ex; }
        __syncthreads();
        if (threadIdx.x == 1023) s_carry = incl;
        __syncthreads();
    }
    if (threadIdx.x == 0) g_off[V_] = s_carry;
}
__global__ void fill_adj_kernel(const int* __restrict__ edges){
    int e = blockIdx.x*256 + threadIdx.x;
    if (e < E_){
        int i = edges[2*e], j = edges[2*e+1];
        int p = atomicAdd(&g_cur[i], 1); g_adj[p] = j;
        int q = atomicAdd(&g_cur[j], 1); g_adj[q] = i;
    }
}

// ---------------- 3) neighbor sum -> bf16 hi/lo ONLY ----------------
__global__ __launch_bounds__(256) void nsum_kernel(const float* __restrict__ x,
                                                   __nv_bfloat16* __restrict__ Sh,
                                                   __nv_bfloat16* __restrict__ Sl){
    int warp = blockIdx.x * 8 + (threadIdx.x >> 5);
    if (warp >= BV_) return;
    int lane = threadIdx.x & 31;
    int b = warp / V_, i = warp - b*V_;
    const float4* xb = (const float4*)(x + (size_t)b*V_*C_);
    float4 acc = make_float4(0.f,0.f,0.f,0.f);
    int p0 = g_off[i], p1 = g_off[i+1];
    for (int p = p0; p < p1; p++){
        int j = g_adj[p];
        float4 v = xb[(size_t)j*32 + lane];
        acc.x += v.x; acc.y += v.y; acc.z += v.z; acc.w += v.w;
    }
    size_t off = (size_t)warp*128 + lane*4;
    *(uint2*)(Sh + off) = make_uint2(bfpair_hi(acc.x, acc.y), bfpair_hi(acc.z, acc.w));
    *(uint2*)(Sl + off) = make_uint2(bfpair_lo(acc.x, acc.y), bfpair_lo(acc.z, acc.w));
}

// ---------------- 3.5) weight transpose + bf16 split ----------------
__global__ void wsplit_all_kernel(const float* __restrict__ w0, const float* __restrict__ w1,
                                  const float* __restrict__ w2, const float* __restrict__ w3,
                                  const float* __restrict__ w4, const float* __restrict__ w5,
                                  __nv_bfloat16* __restrict__ hi, __nv_bfloat16* __restrict__ lo){
    int m = blockIdx.x >> 6;
    const float* w = (m==0)?w0:(m==1)?w1:(m==2)?w2:(m==3)?w3:(m==4)?w4:w5;
    int idx = (blockIdx.x & 63)*256 + threadIdx.x;
    int n = idx & 127, k = idx >> 7;
    float v = w[k*128 + n];
    __nv_bfloat16 h = __float2bfloat16(v);
    hi[m*16384 + n*128 + k] = h;
    lo[m*16384 + n*128 + k] = __float2bfloat16(v - __bfloat162float(h));
}

// ================= 4) PERSISTENT hybrid dual-pipe fused GEMM =================
// Grid = 296 (one wave; bid & bid+148 co-resident, 148%8=4 -> H+F pairing kept).
// Each CTA loops over its type's tiles (stride 148). H CTAs prefetch the next
// tile's [W0h, Xh, Xl] during the epilogue, eliminating per-tile exposed loads.
#define TS_A0 0
#define TS_A1 32768
#define TS_B  65536
#define TSMEM 98304

__global__ __launch_bounds__(256, 2) void hybrid_gemm_kernel(
    const float* __restrict__ X,
    const __nv_bfloat16* __restrict__ Xh, const __nv_bfloat16* __restrict__ Xl,
    const __nv_bfloat16* __restrict__ Sh, const __nv_bfloat16* __restrict__ Sl,
    const float* __restrict__ Wa32, const float* __restrict__ Wb32,
    const __nv_bfloat16* __restrict__ Whi, const __nv_bfloat16* __restrict__ Wlo,
    const float* __restrict__ bias, const float* __restrict__ Z,
    float* __restrict__ Y,
    __nv_bfloat16* __restrict__ Yh, __nv_bfloat16* __restrict__ Yl)
{
    extern __shared__ char smem[];
    const int tid = threadIdx.x;
    const int bid = blockIdx.x;
    const bool useH = (bid & 7) < 4;

    if (useH){
        // ======== tensor-pipe path: persistent, pipelined bf16x3 ========
        uint32_t sbase = smem_to_u32(smem);
        const int l = tid & 31;
        const int wid = tid >> 5;
        const int warp_m = wid >> 2;
        const int warp_n = wid & 3;
        const int ih = ((bid >> 3) << 2) + (bid & 3);    // 0..147

        auto loadT = [&](uint32_t dst, const __nv_bfloat16* src){
            #pragma unroll
            for (int i = 0; i < 8; i++){
                int idx = tid + i*256;
                int row = idx >> 4, c = idx & 15;
                uint32_t off = (uint32_t)(row*256 + ((c ^ ((row & 7)*2)) * 16));
                cpasync16(dst + off, src + (size_t)row*128 + c*8);
            }
        };

        float acc[4][4][4];

        auto mmapass = [&](uint32_t abuf, uint32_t bbuf){
            const int sx = (l & 7) * 2;
            uint32_t a_base = sbase + abuf + (uint32_t)((warp_m*64 + (l & 15)) * 256);
            const int a_choff = (l >> 4);
            uint32_t b_base = sbase + bbuf + (uint32_t)((warp_n*32 + ((l >> 4) << 3) + (l & 7)) * 256);
            const int b_choff = (l >> 3) & 1;
            #pragma unroll
            for (int ks = 0; ks < 8; ks++){
                uint32_t afr[4][4];
                #pragma unroll
                for (int mt = 0; mt < 4; mt++)
                    ldsm4(afr[mt], a_base + mt*4096 + (uint32_t)(((2*ks + a_choff) ^ sx) * 16));
                uint32_t bfr[2][4];
                #pragma unroll
                for (int np = 0; np < 2; np++)
                    ldsm4(bfr[np], b_base + np*4096 + (uint32_t)(((2*ks + b_choff) ^ sx) * 16));
                #pragma unroll
                for (int mt = 0; mt < 4; mt++){
                    #pragma unroll
                    for (int np = 0; np < 2; np++){
                        mma_bf16(acc[mt][2*np],   afr[mt], &bfr[np][0]);
                        mma_bf16(acc[mt][2*np+1], afr[mt], &bfr[np][2]);
                    }
                }
            }
        };

        // prefetch first tile
        {
            long r0 = (long)(((ih >> 2) << 3) + (ih & 3)) * 128;
            loadT(sbase + TS_B,  Whi);
            loadT(sbase + TS_A0, Xh + r0*128);
            loadT(sbase + TS_A1, Xl + r0*128);
            CP_COMMIT();
        }

        #pragma unroll 1
        for (int it = ih; it < HTILES; it += 148){
            const long row0 = (long)(((it >> 2) << 3) + (it & 3)) * 128;
            #pragma unroll
            for (int a=0;a<4;a++)
                #pragma unroll
                for (int b=0;b<4;b++)
                    #pragma unroll
                    for (int c=0;c<4;c++) acc[a][b][c] = 0.f;

            CP_WAIT0(); __syncthreads();           // first-tile / prefetch arrival

            mmapass(TS_A1, TS_B);                  // Xl*W0h
            __syncthreads();
            loadT(sbase + TS_A1, Wlo); CP_COMMIT();
            mmapass(TS_A0, TS_B);                  // Xh*W0h
            CP_WAIT0(); __syncthreads();

            loadT(sbase + TS_B, Sh + row0*128); CP_COMMIT();
            mmapass(TS_A0, TS_A1);                 // Xh*W0l
            CP_WAIT0(); __syncthreads();

            loadT(sbase + TS_A0, Sl + row0*128);
            loadT(sbase + TS_A1, Whi + 16384);
            CP_COMMIT(); CP_WAIT0(); __syncthreads();

            mmapass(TS_A0, TS_A1);                 // Sl*W1h
            __syncthreads();
            loadT(sbase + TS_A0, Wlo + 16384); CP_COMMIT();
            mmapass(TS_B, TS_A1);                  // Sh*W1h
            CP_WAIT0(); __syncthreads();

            mmapass(TS_B, TS_A0);                  // Sh*W1l
            __syncthreads();                       // all reads done before prefetch overwrite

            int nx = it + 148;
            if (nx < HTILES){
                long nr0 = (long)(((nx >> 2) << 3) + (nx & 3)) * 128;
                loadT(sbase + TS_B,  Whi);
                loadT(sbase + TS_A0, Xh + nr0*128);
                loadT(sbase + TS_A1, Xl + nr0*128);
                CP_COMMIT();                       // hidden under epilogue
            }

            // epilogue
            #pragma unroll
            for (int mt = 0; mt < 4; mt++){
                long rg = row0 + warp_m*64 + mt*16 + (l >> 2);
                #pragma unroll
                for (int nt = 0; nt < 4; nt++){
                    int col = warp_n*32 + nt*8 + (l & 3)*2;
                    float2 bv = *(const float2*)(bias + col);
                    float2 v0 = make_float2(acc[mt][nt][0] + bv.x, acc[mt][nt][1] + bv.y);
                    float2 v1 = make_float2(acc[mt][nt][2] + bv.x, acc[mt][nt][3] + bv.y);
                    if (Z){
                        float2 z0 = *(const float2*)(Z + rg*128 + col);
                        float2 z1 = *(const float2*)(Z + (rg+8)*128 + col);
                        v0.x += z0.x; v0.y += z0.y;
                        v1.x += z1.x; v1.y += z1.y;
                    }
                    *(float2*)(Y + rg*128 + col)     = v0;
                    *(float2*)(Y + (rg+8)*128 + col) = v1;
                    if (Yh){
                        *(uint32_t*)(Yh + rg*128 + col)     = bfpair_hi(v0.x, v0.y);
                        *(uint32_t*)(Yl + rg*128 + col)     = bfpair_lo(v0.x, v0.y);
                        *(uint32_t*)(Yh + (rg+8)*128 + col) = bfpair_hi(v1.x, v1.y);
                        *(uint32_t*)(Yl + (rg+8)*128 + col) = bfpair_lo(v1.x, v1.y);
                    }
                }
            }
        }
    } else {
        // ======== FP32 pipe path: persistent ========
        float* sx = (float*)smem;            // [2][16][132]
        float* sw = sx + 2*16*132;           // [2][16][128]
        const int tr = (tid >> 4) * 4;
        const int tc = (tid & 15) * 4;
        const int iff = ((bid >> 3) << 2) + ((bid & 7) - 4);   // 0..147

        unsigned long long acc[8][4];
        float4 rx0, rx1, rw0, rw1;

        #pragma unroll 1
        for (int it = iff; it < HTILES; it += 148){
            const long row0 = (long)(((it >> 2) << 3) + 4 + (it & 3)) * 128;
            #pragma unroll
            for (int r=0;r<8;r++)
                #pragma unroll
                for (int c=0;c<4;c++) acc[r][c] = 0ull;

            auto fetch = [&](int s){
                const float* Wm = (s < 8) ? Wa32 : Wb32;
                const int kx = (s & 7) * 16;
                {
                    int idx = tid;
                    int row = idx >> 2, q = idx & 3;
                    size_t o = (size_t)(row0+row)*128 + kx + q*4;
                    if (s < 8){
                        rx0 = *(const float4*)(X + o);
                    } else {
                        uint2 h2 = *(const uint2*)(Sh + o);
                        uint2 l2 = *(const uint2*)(Sl + o);
                        rx0 = bfpair4_to_f4(h2, l2);
                    }
                    int kr = idx >> 5, cq = idx & 31;
                    rw0 = *(const float4*)(Wm + (size_t)(kx+kr)*128 + cq*4);
                }
                {
                    int idx = tid + 256;
                    int row = idx >> 2, q = idx & 3;
                    size_t o = (size_t)(row0+row)*128 + kx + q*4;
                    if (s < 8){
                        rx1 = *(const float4*)(X + o);
                    } else {
                        uint2 h2 = *(const uint2*)(Sh + o);
                        uint2 l2 = *(const uint2*)(Sl + o);
                        rx1 = bfpair4_to_f4(h2, l2);
                    }
                    int kr = idx >> 5, cq = idx & 31;
                    rw1 = *(const float4*)(Wm + (size_t)(kx+kr)*128 + cq*4);
                }
            };
            auto store = [&](int buf){
                float* xb = sx + buf*2112;
                float* wb = sw + buf*2048;
                {
                    int idx = tid;
                    int row = idx >> 2, q = idx & 3;
                    xb[(q*4+0)*132+row] = rx0.x; xb[(q*4+1)*132+row] = rx0.y;
                    xb[(q*4+2)*132+row] = rx0.z; xb[(q*4+3)*132+row] = rx0.w;
                    int kr = idx >> 5, cq = idx & 31;
                    *(float4*)&wb[kr*128 + cq*4] = rw0;
                }
                {
                    int idx = tid + 256;
                    int row = idx >> 2, q = idx & 3;
                    xb[(q*4+0)*132+row] = rx1.x; xb[(q*4+1)*132+row] = rx1.y;
                    xb[(q*4+2)*132+row] = rx1.z; xb[(q*4+3)*132+row] = rx1.w;
                    int kr = idx >> 5, cq = idx & 31;
                    *(float4*)&wb[kr*128 + cq*4] = rw1;
                }
            };

            fetch(0); store(0);
            __syncthreads();

            #pragma unroll 1
            for (int s = 0; s < 16; s++){
                int buf = s & 1;
                float* xb = sx + buf*2112;
                float* wb = sw + buf*2048;
                if (s < 15) fetch(s+1);
                #pragma unroll
                for (int k = 0; k < 16; k++){
                    float4 xa = *(const float4*)&xb[k*132 + tr];
                    float4 xc = *(const float4*)&xb[k*132 + tr+64];
                    float4 wa = *(const float4*)&wb[k*128 + tc];
                    float4 wc = *(const float4*)&wb[k*128 + tc+64];
                    unsigned long long wp0 = pack2(wa.x, wa.y);
                    unsigned long long wp1 = pack2(wa.z, wa.w);
                    unsigned long long wp2 = pack2(wc.x, wc.y);
                    unsigned long long wp3 = pack2(wc.z, wc.w);
                    float xr[8] = {xa.x,xa.y,xa.z,xa.w, xc.x,xc.y,xc.z,xc.w};
                    #pragma unroll
                    for (int r=0;r<8;r++){
                        unsigned long long ad = pack2(xr[r], xr[r]);
                        ffma2(acc[r][0], ad, wp0);
                        ffma2(acc[r][1], ad, wp1);
                        ffma2(acc[r][2], ad, wp2);
                        ffma2(acc[r][3], ad, wp3);
                    }
                }
                if (s < 15) store((s+1)&1);
                __syncthreads();
            }

            float4 ba = *(const float4*)(bias + tc);
            float4 bb = *(const float4*)(bias + tc + 64);
            #pragma unroll
            for (int r=0;r<8;r++){
                long row = row0 + tr + (r & 3) + ((r >> 2) * 64);
                float2 p0 = unpack2(acc[r][0]), p1 = unpack2(acc[r][1]);
                float2 p2 = unpack2(acc[r][2]), p3 = unpack2(acc[r][3]);
                float4 v0 = make_float4(p0.x + ba.x, p0.y + ba.y, p1.x + ba.z, p1.y + ba.w);
                float4 v1 = make_float4(p2.x + bb.x, p2.y + bb.y, p3.x + bb.z, p3.y + bb.w);
                if (Z){
                    float4 z0 = *(const float4*)(Z + row*128 + tc);
                    float4 z1 = *(const float4*)(Z + row*128 + tc + 64);
                    v0.x += z0.x; v0.y += z0.y; v0.z += z0.z; v0.w += z0.w;
                    v1.x += z1.x; v1.y += z1.y; v1.z += z1.z; v1.w += z1.w;
                }
                *(float4*)(Y + row*128 + tc)      = v0;
                *(float4*)(Y + row*128 + tc + 64) = v1;
                if (Yh){
                    *(uint2*)(Yh + row*128 + tc)      = make_uint2(bfpair_hi(v0.x,v0.y), bfpair_hi(v0.z,v0.w));
                    *(uint2*)(Yl + row*128 + tc)      = make_uint2(bfpair_lo(v0.x,v0.y), bfpair_lo(v0.z,v0.w));
                    *(uint2*)(Yh + row*128 + tc + 64) = make_uint2(bfpair_hi(v1.x,v1.y), bfpair_hi(v1.z,v1.w));
                    *(uint2*)(Yl + row*128 + tc + 64) = make_uint2(bfpair_lo(v1.x,v1.y), bfpair_lo(v1.z,v1.w));
                }
            }
        }
    }
}

// ---------------- launch ----------------
extern "C" void kernel_launch(void* const* d_in, const int* in_sizes, int n_in,
                              void* d_out, int out_size)
{
    const float* img  = (const float*)d_in[0];
    const float* vpos = (const float*)d_in[1];
    const float* vpad = (const float*)d_in[2];
    const int*   edges= (const int*)  d_in[3];
    const float* w0_1 = (const float*)d_in[4];
    const float* b0_1 = (const float*)d_in[5];
    const float* w1_1 = (const float*)d_in[6];
    const float* w0_2 = (const float*)d_in[7];
    const float* b0_2 = (const float*)d_in[8];
    const float* w1_2 = (const float*)d_in[9];
    const float* w0_3 = (const float*)d_in[10];
    const float* b0_3 = (const float*)d_in[11];
    const float* w1_3 = (const float*)d_in[12];
    float* out = (float*)d_out;

    float *pft, *px, *pd, *pt;
    __nv_bfloat16 *pwh, *pwl, *pxh, *pxl, *pdh, *pdl, *psh, *psl;
    cudaGetSymbolAddress((void**)&pft, g_featT);
    cudaGetSymbolAddress((void**)&px,  g_x);
    cudaGetSymbolAddress((void**)&pd,  g_d);
    cudaGetSymbolAddress((void**)&pt,  g_t);
    cudaGetSymbolAddress((void**)&pwh, g_whi);
    cudaGetSymbolAddress((void**)&pwl, g_wlo);
    cudaGetSymbolAddress((void**)&pxh, g_xh);
    cudaGetSymbolAddress((void**)&pxl, g_xl);
    cudaGetSymbolAddress((void**)&pdh, g_dh);
    cudaGetSymbolAddress((void**)&pdl, g_dl);
    cudaGetSymbolAddress((void**)&psh, g_sh);
    cudaGetSymbolAddress((void**)&psl, g_sl);

    cudaFuncSetAttribute(hybrid_gemm_kernel, cudaFuncAttributeMaxDynamicSharedMemorySize, TSMEM);

    transpose_kernel<<<dim3(HW_/32, C_/32, B_), dim3(32,8)>>>(img, pft);
    valign_kernel<<<BV_/8, 256>>>(pft, vpos, vpad, px, pxh, pxl);
    zero_deg_kernel<<<(V_+255)/256, 256>>>();
    count_deg_kernel<<<(E_+255)/256, 256>>>(edges);
    scan_kernel<<<1, 1024>>>();
    fill_adj_kernel<<<(E_+255)/256, 256>>>(edges);
    wsplit_all_kernel<<<384, 256>>>(w0_1, w1_1, w0_2, w1_2, w0_3, w1_3, pwh, pwl);

    // conv1: d = g@W0_1 + b0_1 + nsum(g)@W1_1 ; emits fp32 d + (dh,dl)
    nsum_kernel<<<BV_/8, 256>>>(px, psh, psl);
    hybrid_gemm_kernel<<<PCTAS, 256, TSMEM>>>(px, pxh, pxl, psh, psl,
        w0_1, w1_1, pwh + 0*16384, pwl + 0*16384, b0_1, nullptr, pd, pdh, pdl);
    // conv2: t = d@W0_2 + b0_2 + nsum(d)@W1_2 ; emits fp32 t + (xh,xl)
    nsum_kernel<<<BV_/8, 256>>>(pd, psh, psl);
    hybrid_gemm_kernel<<<PCTAS, 256, TSMEM>>>(pd, pdh, pdl, psh, psl,
        w0_2, w1_2, pwh + 2*16384, pwl + 2*16384, b0_2, nullptr, pt, pxh, pxl);
    // conv3 (+ fused final add of d): fp32 out only
    nsum_kernel<<<BV_/8, 256>>>(pt, psh, psl);
    hybrid_gemm_kernel<<<PCTAS, 256, TSMEM>>>(pt, pxh, pxl, psh, psl,
        w0_3, w1_3, pwh + 4*16384, pwl + 4*16384, b0_3, pd, out, nullptr, nullptr);
}

// round 16
// speedup vs baseline: 1.6461x; 1.2651x over previous
#include <cuda_runtime.h>
#include <cuda_bf16.h>
#include <cstdint>

#define B_ 16
#define V_ 40000
#define C_ 128
#define H_ 56
#define W_ 56
#define E_ 120000
#define HW_ (H_*W_)
#define BV_ (B_*V_)

// ---------------- scratch (device globals; no cudaMalloc allowed) ----------------
__device__ float g_featT[B_*HW_*C_];
__device__ float g_x[BV_*C_];
__device__ float g_d[BV_*C_];
__device__ float g_t[BV_*C_];
__device__ int   g_deg[V_];
__device__ int   g_off[V_+1];
__device__ int   g_cur[V_];
__device__ int   g_adj[2*E_];
__device__ __nv_bfloat16 g_whi[6*128*128];
__device__ __nv_bfloat16 g_wlo[6*128*128];
__device__ __nv_bfloat16 g_xh[BV_*C_];
__device__ __nv_bfloat16 g_xl[BV_*C_];
__device__ __nv_bfloat16 g_dh[BV_*C_];
__device__ __nv_bfloat16 g_dl[BV_*C_];
__device__ __nv_bfloat16 g_sh[BV_*C_];
__device__ __nv_bfloat16 g_sl[BV_*C_];

// ================= helpers =================
__device__ __forceinline__ uint32_t smem_to_u32(const void* p){
    uint32_t a;
    asm("{ .reg .u64 t; cvta.to.shared.u64 t, %1; cvt.u32.u64 %0, t; }" : "=r"(a) : "l"(p));
    return a;
}
__device__ __forceinline__ void ldsm4(uint32_t* r, uint32_t addr){
    asm volatile("ldmatrix.sync.aligned.m8n8.x4.shared.b16 {%0,%1,%2,%3}, [%4];"
        : "=r"(r[0]), "=r"(r[1]), "=r"(r[2]), "=r"(r[3]) : "r"(addr));
}
__device__ __forceinline__ void mma_bf16(float* c, const uint32_t* a, const uint32_t* b){
    asm volatile("mma.sync.aligned.m16n8k16.row.col.f32.bf16.bf16.f32 "
        "{%0,%1,%2,%3}, {%4,%5,%6,%7}, {%8,%9}, {%0,%1,%2,%3};"
        : "+f"(c[0]), "+f"(c[1]), "+f"(c[2]), "+f"(c[3])
        : "r"(a[0]), "r"(a[1]), "r"(a[2]), "r"(a[3]), "r"(b[0]), "r"(b[1]));
}
__device__ __forceinline__ void cpasync16(uint32_t dst, const void* src){
    asm volatile("cp.async.cg.shared.global [%0], [%1], 16;" :: "r"(dst), "l"(src));
}
#define CP_COMMIT() asm volatile("cp.async.commit_group;" ::: "memory")
#define CP_WAIT0()  asm volatile("cp.async.wait_group 0;" ::: "memory")

__device__ __forceinline__ unsigned short bf_hi(float x){
    __nv_bfloat16 h = __float2bfloat16(x);
    return *(unsigned short*)&h;
}
__device__ __forceinline__ unsigned short bf_lo(float x){
    __nv_bfloat16 h = __float2bfloat16(x);
    float r = x - __bfloat162float(h);
    __nv_bfloat16 lo = __float2bfloat16(r);
    return *(unsigned short*)&lo;
}
__device__ __forceinline__ uint32_t bfpair_hi(float a, float b){
    return (uint32_t)bf_hi(a) | ((uint32_t)bf_hi(b) << 16);
}
__device__ __forceinline__ uint32_t bfpair_lo(float a, float b){
    return (uint32_t)bf_lo(a) | ((uint32_t)bf_lo(b) << 16);
}
__device__ __forceinline__ float4 bfpair4_to_f4(uint2 h, uint2 l){
    float2 a = __bfloat1622float2(*(const __nv_bfloat162*)&h.x);
    float2 b = __bfloat1622float2(*(const __nv_bfloat162*)&l.x);
    float2 c = __bfloat1622float2(*(const __nv_bfloat162*)&h.y);
    float2 d = __bfloat1622float2(*(const __nv_bfloat162*)&l.y);
    return make_float4(a.x + b.x, a.y + b.y, c.x + d.x, c.y + d.y);
}
__device__ __forceinline__ unsigned long long pack2(float lo, float hi){
    unsigned long long r;
    asm("mov.b64 %0, {%1, %2};" : "=l"(r) : "f"(lo), "f"(hi));
    return r;
}
__device__ __forceinline__ void ffma2(unsigned long long &acc, unsigned long long a, unsigned long long b){
    asm("fma.rn.f32x2 %0, %1, %2, %0;" : "+l"(acc) : "l"(a), "l"(b));
}
__device__ __forceinline__ float2 unpack2(unsigned long long v){
    float2 f;
    asm("mov.b64 {%0, %1}, %2;" : "=f"(f.x), "=f"(f.y) : "l"(v));
    return f;
}

// ---------------- 0) transpose [B,C,H,W] -> [B,H,W,C] ----------------
__global__ void transpose_kernel(const float* __restrict__ in, float* __restrict__ out){
    __shared__ float tile[32][33];
    int b = blockIdx.z;
    int hw0 = blockIdx.x*32, c0 = blockIdx.y*32;
    int tx = threadIdx.x, ty = threadIdx.y;
    #pragma unroll
    for (int k=0;k<4;k++){
        int c = c0 + ty + k*8;
        tile[ty+k*8][tx] = in[((size_t)(b*C_ + c))*HW_ + hw0 + tx];
    }
    __syncthreads();
    #pragma unroll
    for (int k=0;k<4;k++){
        int hw = hw0 + ty + k*8;
        out[((size_t)b*HW_ + hw)*C_ + c0 + tx] = tile[tx][ty+k*8];
    }
}

// ---------------- 1) vert_align + vertex_padded -> g_x (+ hi/lo split) ----------------
__global__ __launch_bounds__(256) void valign_kernel(
    const float* __restrict__ featT, const float* __restrict__ vpos,
    const float* __restrict__ vpad, float* __restrict__ g,
    __nv_bfloat16* __restrict__ gh, __nv_bfloat16* __restrict__ gl)
{
    int warp = blockIdx.x * 8 + (threadIdx.x >> 5);
    if (warp >= BV_) return;
    int lane = threadIdx.x & 31;
    int b = warp / V_;

    const float* vp = vpos + (size_t)warp*3;
    float fx = (vp[0] + 1.f) * 0.5f * (float)(W_-1);
    float fy = (vp[1] + 1.f) * 0.5f * (float)(H_-1);
    float x0f = floorf(fx), y0f = floorf(fy);
    float wx1 = fx - x0f, wx0 = 1.f - wx1;
    float wy1 = fy - y0f, wy0 = 1.f - wy1;
    int x0 = (int)x0f, y0 = (int)y0f;

    const float4* fb = (const float4*)featT + (size_t)b*HW_*32;
    float4 acc = make_float4(0.f,0.f,0.f,0.f);

    int xs[4] = {x0, x0+1, x0,   x0+1};
    int ys[4] = {y0, y0,   y0+1, y0+1};
    float wt[4] = {wx0*wy0, wx1*wy0, wx0*wy1, wx1*wy1};
    #pragma unroll
    for (int t=0;t<4;t++){
        int xi = xs[t], yi = ys[t];
        if (xi >= 0 && xi < W_ && yi >= 0 && yi < H_){
            float4 f = fb[(size_t)(yi*W_+xi)*32 + lane];
            float w = wt[t];
            acc.x += w*f.x; acc.y += w*f.y; acc.z += w*f.z; acc.w += w*f.w;
        }
    }
    float4 pv = ((const float4*)vpad)[(size_t)warp*32 + lane];
    acc.x += pv.x; acc.y += pv.y; acc.z += pv.z; acc.w += pv.w;
    ((float4*)g)[(size_t)warp*32 + lane] = acc;
    size_t off = (size_t)warp*128 + lane*4;
    *(uint2*)(gh + off) = make_uint2(bfpair_hi(acc.x, acc.y), bfpair_hi(acc.z, acc.w));
    *(uint2*)(gl + off) = make_uint2(bfpair_lo(acc.x, acc.y), bfpair_lo(acc.z, acc.w));
}

// ---------------- 2) CSR build ----------------
__global__ void zero_deg_kernel(){
    int i = blockIdx.x*256 + threadIdx.x;
    if (i < V_) g_deg[i] = 0;
}
__global__ void count_deg_kernel(const int* __restrict__ edges){
    int e = blockIdx.x*256 + threadIdx.x;
    if (e < E_){
        int i = edges[2*e], j = edges[2*e+1];
        atomicAdd(&g_deg[i], 1);
        atomicAdd(&g_deg[j], 1);
    }
}
__global__ void scan_kernel(){
    __shared__ int wsum[32];
    __shared__ int s_carry;
    if (threadIdx.x == 0) s_carry = 0;
    __syncthreads();
    int lane = threadIdx.x & 31, w = threadIdx.x >> 5;
    for (int base = 0; base < V_; base += 1024){
        int i = base + (int)threadIdx.x;
        int v = (i < V_) ? g_deg[i] : 0;
        int x = v;
        #pragma unroll
        for (int d=1; d<32; d<<=1){ int y=__shfl_up_sync(0xffffffffu, x, d); if (lane>=d) x+=y; }
        if (lane == 31) wsum[w] = x;
        __syncthreads();
        if (w == 0){
            int s = wsum[lane];
            #pragma unroll
            for (int d=1; d<32; d<<=1){ int y=__shfl_up_sync(0xffffffffu, s, d); if (lane>=d) s+=y; }
            wsum[lane] = s;
        }
        __syncthreads();
        int incl = x + (w ? wsum[w-1] : 0) + s_carry;
        if (i < V_){ int ex = incl - v; g_off[i] = ex; g_cur[i] = ex; }
        __syncthreads();
        if (threadIdx.x == 1023) s_carry = incl;
        __syncthreads();
    }
    if (threadIdx.x == 0) g_off[V_] = s_carry;
}
__global__ void fill_adj_kernel(const int* __restrict__ edges){
    int e = blockIdx.x*256 + threadIdx.x;
    if (e < E_){
        int i = edges[2*e], j = edges[2*e+1];
        int p = atomicAdd(&g_cur[i], 1); g_adj[p] = j;
        int q = atomicAdd(&g_cur[j], 1); g_adj[q] = i;
    }
}

// ---------------- 3) neighbor sum -> bf16 hi/lo ONLY (unroll x2, dual accumulators for MLP) ----------------
__global__ __launch_bounds__(256) void nsum_kernel(const float* __restrict__ x,
                                                   __nv_bfloat16* __restrict__ Sh,
                                                   __nv_bfloat16* __restrict__ Sl){
    int warp = blockIdx.x * 8 + (threadIdx.x >> 5);
    if (warp >= BV_) return;
    int lane = threadIdx.x & 31;
    int b = warp / V_, i = warp - b*V_;
    const float4* xb = (const float4*)(x + (size_t)b*V_*C_);
    float4 acc0 = make_float4(0.f,0.f,0.f,0.f);
    float4 acc1 = make_float4(0.f,0.f,0.f,0.f);
    int p0 = g_off[i], p1 = g_off[i+1];
    int p = p0;
    for (; p + 2 <= p1; p += 2){
        int j0 = g_adj[p];
        int j1 = g_adj[p+1];
        float4 v0 = xb[(size_t)j0*32 + lane];
        float4 v1 = xb[(size_t)j1*32 + lane];
        acc0.x += v0.x; acc0.y += v0.y; acc0.z += v0.z; acc0.w += v0.w;
        acc1.x += v1.x; acc1.y += v1.y; acc1.z += v1.z; acc1.w += v1.w;
    }
    if (p < p1){
        int j = g_adj[p];
        float4 v = xb[(size_t)j*32 + lane];
        acc0.x += v.x; acc0.y += v.y; acc0.z += v.z; acc0.w += v.w;
    }
    float4 acc = make_float4(acc0.x + acc1.x, acc0.y + acc1.y, acc0.z + acc1.z, acc0.w + acc1.w);
    size_t off = (size_t)warp*128 + lane*4;
    *(uint2*)(Sh + off) = make_uint2(bfpair_hi(acc.x, acc.y), bfpair_hi(acc.z, acc.w));
    *(uint2*)(Sl + off) = make_uint2(bfpair_lo(acc.x, acc.y), bfpair_lo(acc.z, acc.w));
}

// ---------------- 3.5) weight transpose + bf16 split (all 6 in one launch) ----------------
__global__ void wsplit_all_kernel(const float* __restrict__ w0, const float* __restrict__ w1,
                                  const float* __restrict__ w2, const float* __restrict__ w3,
                                  const float* __restrict__ w4, const float* __restrict__ w5,
                                  __nv_bfloat16* __restrict__ hi, __nv_bfloat16* __restrict__ lo){
    int m = blockIdx.x >> 6;
    const float* w = (m==0)?w0:(m==1)?w1:(m==2)?w2:(m==3)?w3:(m==4)?w4:w5;
    int idx = (blockIdx.x & 63)*256 + threadIdx.x;
    int n = idx & 127, k = idx >> 7;
    float v = w[k*128 + n];
    __nv_bfloat16 h = __float2bfloat16(v);
    hi[m*16384 + n*128 + k] = h;
    lo[m*16384 + n*128 + k] = __float2bfloat16(v - __bfloat162float(h));
}

// ================= 4) HYBRID dual-pipe fused GEMM (R13 structure, verified best) =================
// H CTAs (50%, &7<4; deterministic H+F pairing): tensor path, bf16x3, software-pipelined loads.
// F CTAs (50%): exact fp32 fma.rn.f32x2 path; X fp32, S reconstructed from Sh+Sl.
#define TS_A0 0
#define TS_A1 32768
#define TS_B  65536
#define TSMEM 98304

__global__ __launch_bounds__(256, 2) void hybrid_gemm_kernel(
    const float* __restrict__ X,
    const __nv_bfloat16* __restrict__ Xh, const __nv_bfloat16* __restrict__ Xl,
    const __nv_bfloat16* __restrict__ Sh, const __nv_bfloat16* __restrict__ Sl,
    const float* __restrict__ Wa32, const float* __restrict__ Wb32,
    const __nv_bfloat16* __restrict__ Whi, const __nv_bfloat16* __restrict__ Wlo,
    const float* __restrict__ bias, const float* __restrict__ Z,
    float* __restrict__ Y,
    __nv_bfloat16* __restrict__ Yh, __nv_bfloat16* __restrict__ Yl)
{
    extern __shared__ char smem[];
    const int tid = threadIdx.x;
    const long row0 = (long)blockIdx.x * 128;
    const bool useH = (blockIdx.x & 7) < 4;

    if (useH){
        // ======== tensor-pipe path: pipelined load-only bf16x3 ========
        uint32_t sbase = smem_to_u32(smem);
        const int l = tid & 31;
        const int wid = tid >> 5;
        const int warp_m = wid >> 2;
        const int warp_n = wid & 3;

        float acc[4][4][4];
        #pragma unroll
        for (int a=0;a<4;a++)
            #pragma unroll
            for (int b=0;b<4;b++)
                #pragma unroll
                for (int c=0;c<4;c++) acc[a][b][c] = 0.f;

        auto loadT = [&](uint32_t dst, const __nv_bfloat16* src){
            #pragma unroll
            for (int i = 0; i < 8; i++){
                int idx = tid + i*256;
                int row = idx >> 4, c = idx & 15;
                uint32_t off = (uint32_t)(row*256 + ((c ^ ((row & 7)*2)) * 16));
                cpasync16(dst + off, src + (size_t)row*128 + c*8);
            }
        };
        auto mmapass = [&](uint32_t abuf, uint32_t bbuf){
            const int sx = (l & 7) * 2;
            uint32_t a_base = sbase + abuf + (uint32_t)((warp_m*64 + (l & 15)) * 256);
            const int a_choff = (l >> 4);
            uint32_t b_base = sbase + bbuf + (uint32_t)((warp_n*32 + ((l >> 4) << 3) + (l & 7)) * 256);
            const int b_choff = (l >> 3) & 1;
            #pragma unroll
            for (int ks = 0; ks < 8; ks++){
                uint32_t afr[4][4];
                #pragma unroll
                for (int mt = 0; mt < 4; mt++)
                    ldsm4(afr[mt], a_base + mt*4096 + (uint32_t)(((2*ks + a_choff) ^ sx) * 16));
                uint32_t bfr[2][4];
                #pragma unroll
                for (int np = 0; np < 2; np++)
                    ldsm4(bfr[np], b_base + np*4096 + (uint32_t)(((2*ks + b_choff) ^ sx) * 16));
                #pragma unroll
                for (int mt = 0; mt < 4; mt++){
                    #pragma unroll
                    for (int np = 0; np < 2; np++){
                        mma_bf16(acc[mt][2*np],   afr[mt], &bfr[np][0]);
                        mma_bf16(acc[mt][2*np+1], afr[mt], &bfr[np][2]);
                    }
                }
            }
        };

        // ---- pipelined schedule (buffers die at known passes) ----
        loadT(sbase + TS_B,  Whi);
        loadT(sbase + TS_A0, Xh + row0*128);
        loadT(sbase + TS_A1, Xl + row0*128);
        CP_COMMIT(); CP_WAIT0(); __syncthreads();

        mmapass(TS_A1, TS_B);                      // Xl*W0h
        __syncthreads();
        loadT(sbase + TS_A1, Wlo); CP_COMMIT();    // W0l -> A1
        mmapass(TS_A0, TS_B);                      // Xh*W0h
        CP_WAIT0(); __syncthreads();

        loadT(sbase + TS_B, Sh + row0*128); CP_COMMIT();  // Sh -> B
        mmapass(TS_A0, TS_A1);                     // Xh*W0l
        CP_WAIT0(); __syncthreads();

        loadT(sbase + TS_A0, Sl + row0*128);
        loadT(sbase + TS_A1, Whi + 16384);
        CP_COMMIT(); CP_WAIT0(); __syncthreads();

        mmapass(TS_A0, TS_A1);                     // Sl*W1h
        __syncthreads();
        loadT(sbase + TS_A0, Wlo + 16384); CP_COMMIT();
        mmapass(TS_B, TS_A1);                      // Sh*W1h
        CP_WAIT0(); __syncthreads();

        mmapass(TS_B, TS_A0);                      // Sh*W1l

        // epilogue
        #pragma unroll
        for (int mt = 0; mt < 4; mt++){
            long rg = row0 + warp_m*64 + mt*16 + (l >> 2);
            #pragma unroll
            for (int nt = 0; nt < 4; nt++){
                int col = warp_n*32 + nt*8 + (l & 3)*2;
                float2 bv = *(const float2*)(bias + col);
                float2 v0 = make_float2(acc[mt][nt][0] + bv.x, acc[mt][nt][1] + bv.y);
                float2 v1 = make_float2(acc[mt][nt][2] + bv.x, acc[mt][nt][3] + bv.y);
                if (Z){
                    float2 z0 = *(const float2*)(Z + rg*128 + col);
                    float2 z1 = *(const float2*)(Z + (rg+8)*128 + col);
                    v0.x += z0.x; v0.y += z0.y;
                    v1.x += z1.x; v1.y += z1.y;
                }
                *(float2*)(Y + rg*128 + col)     = v0;
                *(float2*)(Y + (rg+8)*128 + col) = v1;
                if (Yh){
                    *(uint32_t*)(Yh + rg*128 + col)     = bfpair_hi(v0.x, v0.y);
                    *(uint32_t*)(Yl + rg*128 + col)     = bfpair_lo(v0.x, v0.y);
                    *(uint32_t*)(Yh + (rg+8)*128 + col) = bfpair_hi(v1.x, v1.y);
                    *(uint32_t*)(Yl + (rg+8)*128 + col) = bfpair_lo(v1.x, v1.y);
                }
            }
        }
    } else {
        // ======== FP32 pipe path (packed fma.rn.f32x2, exact fp32) ========
        float* sx = (float*)smem;            // [2][16][132]
        float* sw = sx + 2*16*132;           // [2][16][128]
        const int tr = (tid >> 4) * 4;
        const int tc = (tid & 15) * 4;

        unsigned long long acc[8][4];
        #pragma unroll
        for (int r=0;r<8;r++)
            #pragma unroll
            for (int c=0;c<4;c++) acc[r][c] = 0ull;

        float4 rx0, rx1, rw0, rw1;

        auto fetch = [&](int s){
            const float* Wm = (s < 8) ? Wa32 : Wb32;
            const int kx = (s & 7) * 16;
            {
                int idx = tid;
                int row = idx >> 2, q = idx & 3;
                size_t o = (size_t)(row0+row)*128 + kx + q*4;
                if (s < 8){
                    rx0 = *(const float4*)(X + o);
                } else {
                    uint2 h2 = *(const uint2*)(Sh + o);
                    uint2 l2 = *(const uint2*)(Sl + o);
                    rx0 = bfpair4_to_f4(h2, l2);
                }
                int kr = idx >> 5, cq = idx & 31;
                rw0 = *(const float4*)(Wm + (size_t)(kx+kr)*128 + cq*4);
            }
            {
                int idx = tid + 256;
                int row = idx >> 2, q = idx & 3;
                size_t o = (size_t)(row0+row)*128 + kx + q*4;
                if (s < 8){
                    rx1 = *(const float4*)(X + o);
                } else {
                    uint2 h2 = *(const uint2*)(Sh + o);
                    uint2 l2 = *(const uint2*)(Sl + o);
                    rx1 = bfpair4_to_f4(h2, l2);
                }
                int kr = idx >> 5, cq = idx & 31;
                rw1 = *(const float4*)(Wm + (size_t)(kx+kr)*128 + cq*4);
            }
        };
        auto store = [&](int buf){
            float* xb = sx + buf*2112;
            float* wb = sw + buf*2048;
            {
                int idx = tid;
                int row = idx >> 2, q = idx & 3;
                xb[(q*4+0)*132+row] = rx0.x; xb[(q*4+1)*132+row] = rx0.y;
                xb[(q*4+2)*132+row] = rx0.z; xb[(q*4+3)*132+row] = rx0.w;
                int kr = idx >> 5, cq = idx & 31;
                *(float4*)&wb[kr*128 + cq*4] = rw0;
            }
            {
                int idx = tid + 256;
                int row = idx >> 2, q = idx & 3;
                xb[(q*4+0)*132+row] = rx1.x; xb[(q*4+1)*132+row] = rx1.y;
                xb[(q*4+2)*132+row] = rx1.z; xb[(q*4+3)*132+row] = rx1.w;
                int kr = idx >> 5, cq = idx & 31;
                *(float4*)&wb[kr*128 + cq*4] = rw1;
            }
        };

        fetch(0); store(0);
        __syncthreads();

        #pragma unroll 1
        for (int s = 0; s < 16; s++){
            int buf = s & 1;
            float* xb = sx + buf*2112;
            float* wb = sw + buf*2048;
            if (s < 15) fetch(s+1);
            #pragma unroll
            for (int k = 0; k < 16; k++){
                float4 xa = *(const float4*)&xb[k*132 + tr];
                float4 xc = *(const float4*)&xb[k*132 + tr+64];
                float4 wa = *(const float4*)&wb[k*128 + tc];
                float4 wc = *(const float4*)&wb[k*128 + tc+64];
                unsigned long long wp0 = pack2(wa.x, wa.y);
                unsigned long long wp1 = pack2(wa.z, wa.w);
                unsigned long long wp2 = pack2(wc.x, wc.y);
                unsigned long long wp3 = pack2(wc.z, wc.w);
                float xr[8] = {xa.x,xa.y,xa.z,xa.w, xc.x,xc.y,xc.z,xc.w};
                #pragma unroll
                for (int r=0;r<8;r++){
                    unsigned long long ad = pack2(xr[r], xr[r]);
                    ffma2(acc[r][0], ad, wp0);
                    ffma2(acc[r][1], ad, wp1);
                    ffma2(acc[r][2], ad, wp2);
                    ffma2(acc[r][3], ad, wp3);
                }
            }
            if (s < 15) store((s+1)&1);
            __syncthreads();
        }

        float4 ba = *(const float4*)(bias + tc);
        float4 bb = *(const float4*)(bias + tc + 64);
        #pragma unroll
        for (int r=0;r<8;r++){
            long row = row0 + tr + (r & 3) + ((r >> 2) * 64);
            float2 p0 = unpack2(acc[r][0]), p1 = unpack2(acc[r][1]);
            float2 p2 = unpack2(acc[r][2]), p3 = unpack2(acc[r][3]);
            float4 v0 = make_float4(p0.x + ba.x, p0.y + ba.y, p1.x + ba.z, p1.y + ba.w);
            float4 v1 = make_float4(p2.x + bb.x, p2.y + bb.y, p3.x + bb.z, p3.y + bb.w);
            if (Z){
                float4 z0 = *(const float4*)(Z + row*128 + tc);
                float4 z1 = *(const float4*)(Z + row*128 + tc + 64);
                v0.x += z0.x; v0.y += z0.y; v0.z += z0.z; v0.w += z0.w;
                v1.x += z1.x; v1.y += z1.y; v1.z += z1.z; v1.w += z1.w;
            }
            *(float4*)(Y + row*128 + tc)      = v0;
            *(float4*)(Y + row*128 + tc + 64) = v1;
            if (Yh){
                *(uint2*)(Yh + row*128 + tc)      = make_uint2(bfpair_hi(v0.x,v0.y), bfpair_hi(v0.z,v0.w));
                *(uint2*)(Yl + row*128 + tc)      = make_uint2(bfpair_lo(v0.x,v0.y), bfpair_lo(v0.z,v0.w));
                *(uint2*)(Yh + row*128 + tc + 64) = make_uint2(bfpair_hi(v1.x,v1.y), bfpair_hi(v1.z,v1.w));
                *(uint2*)(Yl + row*128 + tc + 64) = make_uint2(bfpair_lo(v1.x,v1.y), bfpair_lo(v1.z,v1.w));
            }
        }
    }
}

// ---------------- launch ----------------
extern "C" void kernel_launch(void* const* d_in, const int* in_sizes, int n_in,
                              void* d_out, int out_size)
{
    const float* img  = (const float*)d_in[0];
    const float* vpos = (const float*)d_in[1];
    const float* vpad = (const float*)d_in[2];
    const int*   edges= (const int*)  d_in[3];
    const float* w0_1 = (const float*)d_in[4];
    const float* b0_1 = (const float*)d_in[5];
    const float* w1_1 = (const float*)d_in[6];
    const float* w0_2 = (const float*)d_in[7];
    const float* b0_2 = (const float*)d_in[8];
    const float* w1_2 = (const float*)d_in[9];
    const float* w0_3 = (const float*)d_in[10];
    const float* b0_3 = (const float*)d_in[11];
    const float* w1_3 = (const float*)d_in[12];
    float* out = (float*)d_out;

    float *pft, *px, *pd, *pt;
    __nv_bfloat16 *pwh, *pwl, *pxh, *pxl, *pdh, *pdl, *psh, *psl;
    cudaGetSymbolAddress((void**)&pft, g_featT);
    cudaGetSymbolAddress((void**)&px,  g_x);
    cudaGetSymbolAddress((void**)&pd,  g_d);
    cudaGetSymbolAddress((void**)&pt,  g_t);
    cudaGetSymbolAddress((void**)&pwh, g_whi);
    cudaGetSymbolAddress((void**)&pwl, g_wlo);
    cudaGetSymbolAddress((void**)&pxh, g_xh);
    cudaGetSymbolAddress((void**)&pxl, g_xl);
    cudaGetSymbolAddress((void**)&pdh, g_dh);
    cudaGetSymbolAddress((void**)&pdl, g_dl);
    cudaGetSymbolAddress((void**)&psh, g_sh);
    cudaGetSymbolAddress((void**)&psl, g_sl);

    cudaFuncSetAttribute(hybrid_gemm_kernel, cudaFuncAttributeMaxDynamicSharedMemorySize, TSMEM);

    transpose_kernel<<<dim3(HW_/32, C_/32, B_), dim3(32,8)>>>(img, pft);
    valign_kernel<<<BV_/8, 256>>>(pft, vpos, vpad, px, pxh, pxl);
    zero_deg_kernel<<<(V_+255)/256, 256>>>();
    count_deg_kernel<<<(E_+255)/256, 256>>>(edges);
    scan_kernel<<<1, 1024>>>();
    fill_adj_kernel<<<(E_+255)/256, 256>>>(edges);
    wsplit_all_kernel<<<384, 256>>>(w0_1, w1_1, w0_2, w1_2, w0_3, w1_3, pwh, pwl);

    // conv1: d = g@W0_1 + b0_1 + nsum(g)@W1_1 ; emits fp32 d + (dh,dl)
    nsum_kernel<<<BV_/8, 256>>>(px, psh, psl);
    hybrid_gemm_kernel<<<BV_/128, 256, TSMEM>>>(px, pxh, pxl, psh, psl,
        w0_1, w1_1, pwh + 0*16384, pwl + 0*16384, b0_1, nullptr, pd, pdh, pdl);
    // conv2: t = d@W0_2 + b0_2 + nsum(d)@W1_2 ; emits fp32 t + (xh,xl)
    nsum_kernel<<<BV_/8, 256>>>(pd, psh, psl);
    hybrid_gemm_kernel<<<BV_/128, 256, TSMEM>>>(pd, pdh, pdl, psh, psl,
        w0_2, w1_2, pwh + 2*16384, pwl + 2*16384, b0_2, nullptr, pt, pxh, pxl);
    // conv3 (+ fused final add of d): fp32 out only
    nsum_kernel<<<BV_/8, 256>>>(pt, psh, psl);
    hybrid_gemm_kernel<<<BV_/128, 256, TSMEM>>>(pt, pxh, pxl, psh, psl,
        w0_3, w1_3, pwh + 4*16384, pwl + 4*16384, b0_3, pd, out, nullptr, nullptr);
}

// round 17
// speedup vs baseline: 1.6683x; 1.0135x over previous
#include <cuda_runtime.h>
#include <cuda_bf16.h>
#include <cstdint>

#define B_ 16
#define V_ 40000
#define C_ 128
#define H_ 56
#define W_ 56
#define E_ 120000
#define HW_ (H_*W_)
#define BV_ (B_*V_)

// ---------------- scratch (device globals; no cudaMalloc allowed) ----------------
__device__ float g_featT[B_*HW_*C_];
__device__ float g_x[BV_*C_];
__device__ float g_d[BV_*C_];
__device__ float g_t[BV_*C_];
__device__ int   g_deg[V_];
__device__ int   g_off[V_+1];
__device__ int   g_cur[V_];
__device__ int   g_adj[2*E_];
__device__ __nv_bfloat16 g_whi[6*128*128];
__device__ __nv_bfloat16 g_wlo[6*128*128];
__device__ __nv_bfloat16 g_xh[BV_*C_];
__device__ __nv_bfloat16 g_xl[BV_*C_];
__device__ __nv_bfloat16 g_dh[BV_*C_];
__device__ __nv_bfloat16 g_dl[BV_*C_];
__device__ __nv_bfloat16 g_sh[BV_*C_];
__device__ __nv_bfloat16 g_sl[BV_*C_];

// ================= helpers =================
__device__ __forceinline__ uint32_t smem_to_u32(const void* p){
    uint32_t a;
    asm("{ .reg .u64 t; cvta.to.shared.u64 t, %1; cvt.u32.u64 %0, t; }" : "=r"(a) : "l"(p));
    return a;
}
__device__ __forceinline__ void ldsm4(uint32_t* r, uint32_t addr){
    asm volatile("ldmatrix.sync.aligned.m8n8.x4.shared.b16 {%0,%1,%2,%3}, [%4];"
        : "=r"(r[0]), "=r"(r[1]), "=r"(r[2]), "=r"(r[3]) : "r"(addr));
}
__device__ __forceinline__ void mma_bf16(float* c, const uint32_t* a, const uint32_t* b){
    asm volatile("mma.sync.aligned.m16n8k16.row.col.f32.bf16.bf16.f32 "
        "{%0,%1,%2,%3}, {%4,%5,%6,%7}, {%8,%9}, {%0,%1,%2,%3};"
        : "+f"(c[0]), "+f"(c[1]), "+f"(c[2]), "+f"(c[3])
        : "r"(a[0]), "r"(a[1]), "r"(a[2]), "r"(a[3]), "r"(b[0]), "r"(b[1]));
}
__device__ __forceinline__ void cpasync16(uint32_t dst, const void* src){
    asm volatile("cp.async.cg.shared.global [%0], [%1], 16;" :: "r"(dst), "l"(src));
}
#define CP_COMMIT() asm volatile("cp.async.commit_group;" ::: "memory")
#define CP_WAIT0()  asm volatile("cp.async.wait_group 0;" ::: "memory")
#define CP_WAIT1()  asm volatile("cp.async.wait_group 1;" ::: "memory")

__device__ __forceinline__ unsigned short bf_hi(float x){
    __nv_bfloat16 h = __float2bfloat16(x);
    return *(unsigned short*)&h;
}
__device__ __forceinline__ unsigned short bf_lo(float x){
    __nv_bfloat16 h = __float2bfloat16(x);
    float r = x - __bfloat162float(h);
    __nv_bfloat16 lo = __float2bfloat16(r);
    return *(unsigned short*)&lo;
}
__device__ __forceinline__ uint32_t bfpair_hi(float a, float b){
    return (uint32_t)bf_hi(a) | ((uint32_t)bf_hi(b) << 16);
}
__device__ __forceinline__ uint32_t bfpair_lo(float a, float b){
    return (uint32_t)bf_lo(a) | ((uint32_t)bf_lo(b) << 16);
}
__device__ __forceinline__ float4 bfpair4_to_f4(uint2 h, uint2 l){
    float2 a = __bfloat1622float2(*(const __nv_bfloat162*)&h.x);
    float2 b = __bfloat1622float2(*(const __nv_bfloat162*)&l.x);
    float2 c = __bfloat1622float2(*(const __nv_bfloat162*)&h.y);
    float2 d = __bfloat1622float2(*(const __nv_bfloat162*)&l.y);
    return make_float4(a.x + b.x, a.y + b.y, c.x + d.x, c.y + d.y);
}
__device__ __forceinline__ unsigned long long pack2(float lo, float hi){
    unsigned long long r;
    asm("mov.b64 %0, {%1, %2};" : "=l"(r) : "f"(lo), "f"(hi));
    return r;
}
__device__ __forceinline__ void ffma2(unsigned long long &acc, unsigned long long a, unsigned long long b){
    asm("fma.rn.f32x2 %0, %1, %2, %0;" : "+l"(acc) : "l"(a), "l"(b));
}
__device__ __forceinline__ float2 unpack2(unsigned long long v){
    float2 f;
    asm("mov.b64 {%0, %1}, %2;" : "=f"(f.x), "=f"(f.y) : "l"(v));
    return f;
}

// ---------------- 0) transpose [B,C,H,W] -> [B,H,W,C] ----------------
__global__ void transpose_kernel(const float* __restrict__ in, float* __restrict__ out){
    __shared__ float tile[32][33];
    int b = blockIdx.z;
    int hw0 = blockIdx.x*32, c0 = blockIdx.y*32;
    int tx = threadIdx.x, ty = threadIdx.y;
    #pragma unroll
    for (int k=0;k<4;k++){
        int c = c0 + ty + k*8;
        tile[ty+k*8][tx] = in[((size_t)(b*C_ + c))*HW_ + hw0 + tx];
    }
    __syncthreads();
    #pragma unroll
    for (int k=0;k<4;k++){
        int hw = hw0 + ty + k*8;
        out[((size_t)b*HW_ + hw)*C_ + c0 + tx] = tile[tx][ty+k*8];
    }
}

// ---------------- 1) vert_align + vertex_padded -> g_x (+ hi/lo split) ----------------
__global__ __launch_bounds__(256) void valign_kernel(
    const float* __restrict__ featT, const float* __restrict__ vpos,
    const float* __restrict__ vpad, float* __restrict__ g,
    __nv_bfloat16* __restrict__ gh, __nv_bfloat16* __restrict__ gl)
{
    int warp = blockIdx.x * 8 + (threadIdx.x >> 5);
    if (warp >= BV_) return;
    int lane = threadIdx.x & 31;
    int b = warp / V_;

    const float* vp = vpos + (size_t)warp*3;
    float fx = (vp[0] + 1.f) * 0.5f * (float)(W_-1);
    float fy = (vp[1] + 1.f) * 0.5f * (float)(H_-1);
    float x0f = floorf(fx), y0f = floorf(fy);
    float wx1 = fx - x0f, wx0 = 1.f - wx1;
    float wy1 = fy - y0f, wy0 = 1.f - wy1;
    int x0 = (int)x0f, y0 = (int)y0f;

    const float4* fb = (const float4*)featT + (size_t)b*HW_*32;
    float4 acc = make_float4(0.f,0.f,0.f,0.f);

    int xs[4] = {x0, x0+1, x0,   x0+1};
    int ys[4] = {y0, y0,   y0+1, y0+1};
    float wt[4] = {wx0*wy0, wx1*wy0, wx0*wy1, wx1*wy1};
    #pragma unroll
    for (int t=0;t<4;t++){
        int xi = xs[t], yi = ys[t];
        if (xi >= 0 && xi < W_ && yi >= 0 && yi < H_){
            float4 f = fb[(size_t)(yi*W_+xi)*32 + lane];
            float w = wt[t];
            acc.x += w*f.x; acc.y += w*f.y; acc.z += w*f.z; acc.w += w*f.w;
        }
    }
    float4 pv = ((const float4*)vpad)[(size_t)warp*32 + lane];
    acc.x += pv.x; acc.y += pv.y; acc.z += pv.z; acc.w += pv.w;
    ((float4*)g)[(size_t)warp*32 + lane] = acc;
    size_t off = (size_t)warp*128 + lane*4;
    *(uint2*)(gh + off) = make_uint2(bfpair_hi(acc.x, acc.y), bfpair_hi(acc.z, acc.w));
    *(uint2*)(gl + off) = make_uint2(bfpair_lo(acc.x, acc.y), bfpair_lo(acc.z, acc.w));
}

// ---------------- 2) CSR build ----------------
__global__ void zero_deg_kernel(){
    int i = blockIdx.x*256 + threadIdx.x;
    if (i < V_) g_deg[i] = 0;
}
__global__ void count_deg_kernel(const int* __restrict__ edges){
    int e = blockIdx.x*256 + threadIdx.x;
    if (e < E_){
        int i = edges[2*e], j = edges[2*e+1];
        atomicAdd(&g_deg[i], 1);
        atomicAdd(&g_deg[j], 1);
    }
}
__global__ void scan_kernel(){
    __shared__ int wsum[32];
    __shared__ int s_carry;
    if (threadIdx.x == 0) s_carry = 0;
    __syncthreads();
    int lane = threadIdx.x & 31, w = threadIdx.x >> 5;
    for (int base = 0; base < V_; base += 1024){
        int i = base + (int)threadIdx.x;
        int v = (i < V_) ? g_deg[i] : 0;
        int x = v;
        #pragma unroll
        for (int d=1; d<32; d<<=1){ int y=__shfl_up_sync(0xffffffffu, x, d); if (lane>=d) x+=y; }
        if (lane == 31) wsum[w] = x;
        __syncthreads();
        if (w == 0){
            int s = wsum[lane];
            #pragma unroll
            for (int d=1; d<32; d<<=1){ int y=__shfl_up_sync(0xffffffffu, s, d); if (lane>=d) s+=y; }
            wsum[lane] = s;
        }
        __syncthreads();
        int incl = x + (w ? wsum[w-1] : 0) + s_carry;
        if (i < V_){ int ex = incl - v; g_off[i] = ex; g_cur[i] = ex; }
        __syncthreads();
        if (threadIdx.x == 1023) s_carry = incl;
        __syncthreads();
    }
    if (threadIdx.x == 0) g_off[V_] = s_carry;
}
__global__ void fill_adj_kernel(const int* __restrict__ edges){
    int e = blockIdx.x*256 + threadIdx.x;
    if (e < E_){
        int i = edges[2*e], j = edges[2*e+1];
        int p = atomicAdd(&g_cur[i], 1); g_adj[p] = j;
        int q = atomicAdd(&g_cur[j], 1); g_adj[q] = i;
    }
}

// ---------------- 3) neighbor sum -> bf16 hi/lo ONLY (R13 simple loop — verified best) ----------------
__global__ __launch_bounds__(256) void nsum_kernel(const float* __restrict__ x,
                                                   __nv_bfloat16* __restrict__ Sh,
                                                   __nv_bfloat16* __restrict__ Sl){
    int warp = blockIdx.x * 8 + (threadIdx.x >> 5);
    if (warp >= BV_) return;
    int lane = threadIdx.x & 31;
    int b = warp / V_, i = warp - b*V_;
    const float4* xb = (const float4*)(x + (size_t)b*V_*C_);
    float4 acc = make_float4(0.f,0.f,0.f,0.f);
    int p0 = g_off[i], p1 = g_off[i+1];
    for (int p = p0; p < p1; p++){
        int j = g_adj[p];
        float4 v = xb[(size_t)j*32 + lane];
        acc.x += v.x; acc.y += v.y; acc.z += v.z; acc.w += v.w;
    }
    size_t off = (size_t)warp*128 + lane*4;
    *(uint2*)(Sh + off) = make_uint2(bfpair_hi(acc.x, acc.y), bfpair_hi(acc.z, acc.w));
    *(uint2*)(Sl + off) = make_uint2(bfpair_lo(acc.x, acc.y), bfpair_lo(acc.z, acc.w));
}

// ---------------- 3.5) weight transpose + bf16 split (all 6 in one launch) ----------------
__global__ void wsplit_all_kernel(const float* __restrict__ w0, const float* __restrict__ w1,
                                  const float* __restrict__ w2, const float* __restrict__ w3,
                                  const float* __restrict__ w4, const float* __restrict__ w5,
                                  __nv_bfloat16* __restrict__ hi, __nv_bfloat16* __restrict__ lo){
    int m = blockIdx.x >> 6;
    const float* w = (m==0)?w0:(m==1)?w1:(m==2)?w2:(m==3)?w3:(m==4)?w4:w5;
    int idx = (blockIdx.x & 63)*256 + threadIdx.x;
    int n = idx & 127, k = idx >> 7;
    float v = w[k*128 + n];
    __nv_bfloat16 h = __float2bfloat16(v);
    hi[m*16384 + n*128 + k] = h;
    lo[m*16384 + n*128 + k] = __float2bfloat16(v - __bfloat162float(h));
}

// ================= 4) HYBRID dual-pipe fused GEMM (R13 + split initial commit group) =================
// H CTAs (50%, &7<4; deterministic H+F pairing): tensor path, bf16x3, software-pipelined loads;
//   initial load split into {W0h,Xl} + {Xh} groups so Xh hides under the first mmapass.
// F CTAs (50%): exact fp32 fma.rn.f32x2 path; X fp32, S reconstructed from Sh+Sl.
#define TS_A0 0
#define TS_A1 32768
#define TS_B  65536
#define TSMEM 98304

__global__ __launch_bounds__(256, 2) void hybrid_gemm_kernel(
    const float* __restrict__ X,
    const __nv_bfloat16* __restrict__ Xh, const __nv_bfloat16* __restrict__ Xl,
    const __nv_bfloat16* __restrict__ Sh, const __nv_bfloat16* __restrict__ Sl,
    const float* __restrict__ Wa32, const float* __restrict__ Wb32,
    const __nv_bfloat16* __restrict__ Whi, const __nv_bfloat16* __restrict__ Wlo,
    const float* __restrict__ bias, const float* __restrict__ Z,
    float* __restrict__ Y,
    __nv_bfloat16* __restrict__ Yh, __nv_bfloat16* __restrict__ Yl)
{
    extern __shared__ char smem[];
    const int tid = threadIdx.x;
    const long row0 = (long)blockIdx.x * 128;
    const bool useH = (blockIdx.x & 7) < 4;

    if (useH){
        // ======== tensor-pipe path: pipelined load-only bf16x3 ========
        uint32_t sbase = smem_to_u32(smem);
        const int l = tid & 31;
        const int wid = tid >> 5;
        const int warp_m = wid >> 2;
        const int warp_n = wid & 3;

        float acc[4][4][4];
        #pragma unroll
        for (int a=0;a<4;a++)
            #pragma unroll
            for (int b=0;b<4;b++)
                #pragma unroll
                for (int c=0;c<4;c++) acc[a][b][c] = 0.f;

        auto loadT = [&](uint32_t dst, const __nv_bfloat16* src){
            #pragma unroll
            for (int i = 0; i < 8; i++){
                int idx = tid + i*256;
                int row = idx >> 4, c = idx & 15;
                uint32_t off = (uint32_t)(row*256 + ((c ^ ((row & 7)*2)) * 16));
                cpasync16(dst + off, src + (size_t)row*128 + c*8);
            }
        };
        auto mmapass = [&](uint32_t abuf, uint32_t bbuf){
            const int sx = (l & 7) * 2;
            uint32_t a_base = sbase + abuf + (uint32_t)((warp_m*64 + (l & 15)) * 256);
            const int a_choff = (l >> 4);
            uint32_t b_base = sbase + bbuf + (uint32_t)((warp_n*32 + ((l >> 4) << 3) + (l & 7)) * 256);
            const int b_choff = (l >> 3) & 1;
            #pragma unroll
            for (int ks = 0; ks < 8; ks++){
                uint32_t afr[4][4];
                #pragma unroll
                for (int mt = 0; mt < 4; mt++)
                    ldsm4(afr[mt], a_base + mt*4096 + (uint32_t)(((2*ks + a_choff) ^ sx) * 16));
                uint32_t bfr[2][4];
                #pragma unroll
                for (int np = 0; np < 2; np++)
                    ldsm4(bfr[np], b_base + np*4096 + (uint32_t)(((2*ks + b_choff) ^ sx) * 16));
                #pragma unroll
                for (int mt = 0; mt < 4; mt++){
                    #pragma unroll
                    for (int np = 0; np < 2; np++){
                        mma_bf16(acc[mt][2*np],   afr[mt], &bfr[np][0]);
                        mma_bf16(acc[mt][2*np+1], afr[mt], &bfr[np][2]);
                    }
                }
            }
        };

        // ---- pipelined schedule (split initial group: Xh hides under first pass) ----
        loadT(sbase + TS_B,  Whi);
        loadT(sbase + TS_A1, Xl + row0*128);
        CP_COMMIT();                               // g0: {W0h, Xl}
        loadT(sbase + TS_A0, Xh + row0*128);
        CP_COMMIT();                               // g1: {Xh}
        CP_WAIT1(); __syncthreads();               // g0 ready; g1 in flight

        mmapass(TS_A1, TS_B);                      // Xl*W0h  (Xh loading underneath)
        __syncthreads();                           // A1 free
        loadT(sbase + TS_A1, Wlo); CP_COMMIT();    // g2: {W0l}
        CP_WAIT1(); __syncthreads();               // g1 (Xh) ready; g2 in flight
        mmapass(TS_A0, TS_B);                      // Xh*W0h
        CP_WAIT0(); __syncthreads();               // W0l ready; B free

        loadT(sbase + TS_B, Sh + row0*128); CP_COMMIT();  // Sh -> B
        mmapass(TS_A0, TS_A1);                     // Xh*W0l
        CP_WAIT0(); __syncthreads();               // Sh ready; A0/A1 free

        loadT(sbase + TS_A0, Sl + row0*128);
        loadT(sbase + TS_A1, Whi + 16384);
        CP_COMMIT(); CP_WAIT0(); __syncthreads();

        mmapass(TS_A0, TS_A1);                     // Sl*W1h
        __syncthreads();
        loadT(sbase + TS_A0, Wlo + 16384); CP_COMMIT();
        mmapass(TS_B, TS_A1);                      // Sh*W1h
        CP_WAIT0(); __syncthreads();

        mmapass(TS_B, TS_A0);                      // Sh*W1l

        // epilogue
        #pragma unroll
        for (int mt = 0; mt < 4; mt++){
            long rg = row0 + warp_m*64 + mt*16 + (l >> 2);
            #pragma unroll
            for (int nt = 0; nt < 4; nt++){
                int col = warp_n*32 + nt*8 + (l & 3)*2;
                float2 bv = *(const float2*)(bias + col);
                float2 v0 = make_float2(acc[mt][nt][0] + bv.x, acc[mt][nt][1] + bv.y);
                float2 v1 = make_float2(acc[mt][nt][2] + bv.x, acc[mt][nt][3] + bv.y);
                if (Z){
                    float2 z0 = *(const float2*)(Z + rg*128 + col);
                    float2 z1 = *(const float2*)(Z + (rg+8)*128 + col);
                    v0.x += z0.x; v0.y += z0.y;
                    v1.x += z1.x; v1.y += z1.y;
                }
                *(float2*)(Y + rg*128 + col)     = v0;
                *(float2*)(Y + (rg+8)*128 + col) = v1;
                if (Yh){
                    *(uint32_t*)(Yh + rg*128 + col)     = bfpair_hi(v0.x, v0.y);
                    *(uint32_t*)(Yl + rg*128 + col)     = bfpair_lo(v0.x, v0.y);
                    *(uint32_t*)(Yh + (rg+8)*128 + col) = bfpair_hi(v1.x, v1.y);
                    *(uint32_t*)(Yl + (rg+8)*128 + col) = bfpair_lo(v1.x, v1.y);
                }
            }
        }
    } else {
        // ======== FP32 pipe path (packed fma.rn.f32x2, exact fp32) ========
        float* sx = (float*)smem;            // [2][16][132]
        float* sw = sx + 2*16*132;           // [2][16][128]
        const int tr = (tid >> 4) * 4;
        const int tc = (tid & 15) * 4;

        unsigned long long acc[8][4];
        #pragma unroll
        for (int r=0;r<8;r++)
            #pragma unroll
            for (int c=0;c<4;c++) acc[r][c] = 0ull;

        float4 rx0, rx1, rw0, rw1;

        auto fetch = [&](int s){
            const float* Wm = (s < 8) ? Wa32 : Wb32;
            const int kx = (s & 7) * 16;
            {
                int idx = tid;
                int row = idx >> 2, q = idx & 3;
                size_t o = (size_t)(row0+row)*128 + kx + q*4;
                if (s < 8){
                    rx0 = *(const float4*)(X + o);
                } else {
                    uint2 h2 = *(const uint2*)(Sh + o);
                    uint2 l2 = *(const uint2*)(Sl + o);
                    rx0 = bfpair4_to_f4(h2, l2);
                }
                int kr = idx >> 5, cq = idx & 31;
                rw0 = *(const float4*)(Wm + (size_t)(kx+kr)*128 + cq*4);
            }
            {
                int idx = tid + 256;
                int row = idx >> 2, q = idx & 3;
                size_t o = (size_t)(row0+row)*128 + kx + q*4;
                if (s < 8){
                    rx1 = *(const float4*)(X + o);
                } else {
                    uint2 h2 = *(const uint2*)(Sh + o);
                    uint2 l2 = *(const uint2*)(Sl + o);
                    rx1 = bfpair4_to_f4(h2, l2);
                }
                int kr = idx >> 5, cq = idx & 31;
                rw1 = *(const float4*)(Wm + (size_t)(kx+kr)*128 + cq*4);
            }
        };
        auto store = [&](int buf){
            float* xb = sx + buf*2112;
            float* wb = sw + buf*2048;
            {
                int idx = tid;
                int row = idx >> 2, q = idx & 3;
                xb[(q*4+0)*132+row] = rx0.x; xb[(q*4+1)*132+row] = rx0.y;
                xb[(q*4+2)*132+row] = rx0.z; xb[(q*4+3)*132+row] = rx0.w;
                int kr = idx >> 5, cq = idx & 31;
                *(float4*)&wb[kr*128 + cq*4] = rw0;
            }
            {
                int idx = tid + 256;
                int row = idx >> 2, q = idx & 3;
                xb[(q*4+0)*132+row] = rx1.x; xb[(q*4+1)*132+row] = rx1.y;
                xb[(q*4+2)*132+row] = rx1.z; xb[(q*4+3)*132+row] = rx1.w;
                int kr = idx >> 5, cq = idx & 31;
                *(float4*)&wb[kr*128 + cq*4] = rw1;
            }
        };

        fetch(0); store(0);
        __syncthreads();

        #pragma unroll 1
        for (int s = 0; s < 16; s++){
            int buf = s & 1;
            float* xb = sx + buf*2112;
            float* wb = sw + buf*2048;
            if (s < 15) fetch(s+1);
            #pragma unroll
            for (int k = 0; k < 16; k++){
                float4 xa = *(const float4*)&xb[k*132 + tr];
                float4 xc = *(const float4*)&xb[k*132 + tr+64];
                float4 wa = *(const float4*)&wb[k*128 + tc];
                float4 wc = *(const float4*)&wb[k*128 + tc+64];
                unsigned long long wp0 = pack2(wa.x, wa.y);
                unsigned long long wp1 = pack2(wa.z, wa.w);
                unsigned long long wp2 = pack2(wc.x, wc.y);
                unsigned long long wp3 = pack2(wc.z, wc.w);
                float xr[8] = {xa.x,xa.y,xa.z,xa.w, xc.x,xc.y,xc.z,xc.w};
                #pragma unroll
                for (int r=0;r<8;r++){
                    unsigned long long ad = pack2(xr[r], xr[r]);
                    ffma2(acc[r][0], ad, wp0);
                    ffma2(acc[r][1], ad, wp1);
                    ffma2(acc[r][2], ad, wp2);
                    ffma2(acc[r][3], ad, wp3);
                }
            }
            if (s < 15) store((s+1)&1);
            __syncthreads();
        }

        float4 ba = *(const float4*)(bias + tc);
        float4 bb = *(const float4*)(bias + tc + 64);
        #pragma unroll
        for (int r=0;r<8;r++){
            long row = row0 + tr + (r & 3) + ((r >> 2) * 64);
            float2 p0 = unpack2(acc[r][0]), p1 = unpack2(acc[r][1]);
            float2 p2 = unpack2(acc[r][2]), p3 = unpack2(acc[r][3]);
            float4 v0 = make_float4(p0.x + ba.x, p0.y + ba.y, p1.x + ba.z, p1.y + ba.w);
            float4 v1 = make_float4(p2.x + bb.x, p2.y + bb.y, p3.x + bb.z, p3.y + bb.w);
            if (Z){
                float4 z0 = *(const float4*)(Z + row*128 + tc);
                float4 z1 = *(const float4*)(Z + row*128 + tc + 64);
                v0.x += z0.x; v0.y += z0.y; v0.z += z0.z; v0.w += z0.w;
                v1.x += z1.x; v1.y += z1.y; v1.z += z1.z; v1.w += z1.w;
            }
            *(float4*)(Y + row*128 + tc)      = v0;
            *(float4*)(Y + row*128 + tc + 64) = v1;
            if (Yh){
                *(uint2*)(Yh + row*128 + tc)      = make_uint2(bfpair_hi(v0.x,v0.y), bfpair_hi(v0.z,v0.w));
                *(uint2*)(Yl + row*128 + tc)      = make_uint2(bfpair_lo(v0.x,v0.y), bfpair_lo(v0.z,v0.w));
                *(uint2*)(Yh + row*128 + tc + 64) = make_uint2(bfpair_hi(v1.x,v1.y), bfpair_hi(v1.z,v1.w));
                *(uint2*)(Yl + row*128 + tc + 64) = make_uint2(bfpair_lo(v1.x,v1.y), bfpair_lo(v1.z,v1.w));
            }
        }
    }
}

// ---------------- launch ----------------
extern "C" void kernel_launch(void* const* d_in, const int* in_sizes, int n_in,
                              void* d_out, int out_size)
{
    const float* img  = (const float*)d_in[0];
    const float* vpos = (const float*)d_in[1];
    const float* vpad = (const float*)d_in[2];
    const int*   edges= (const int*)  d_in[3];
    const float* w0_1 = (const float*)d_in[4];
    const float* b0_1 = (const float*)d_in[5];
    const float* w1_1 = (const float*)d_in[6];
    const float* w0_2 = (const float*)d_in[7];
    const float* b0_2 = (const float*)d_in[8];
    const float* w1_2 = (const float*)d_in[9];
    const float* w0_3 = (const float*)d_in[10];
    const float* b0_3 = (const float*)d_in[11];
    const float* w1_3 = (const float*)d_in[12];
    float* out = (float*)d_out;

    float *pft, *px, *pd, *pt;
    __nv_bfloat16 *pwh, *pwl, *pxh, *pxl, *pdh, *pdl, *psh, *psl;
    cudaGetSymbolAddress((void**)&pft, g_featT);
    cudaGetSymbolAddress((void**)&px,  g_x);
    cudaGetSymbolAddress((void**)&pd,  g_d);
    cudaGetSymbolAddress((void**)&pt,  g_t);
    cudaGetSymbolAddress((void**)&pwh, g_whi);
    cudaGetSymbolAddress((void**)&pwl, g_wlo);
    cudaGetSymbolAddress((void**)&pxh, g_xh);
    cudaGetSymbolAddress((void**)&pxl, g_xl);
    cudaGetSymbolAddress((void**)&pdh, g_dh);
    cudaGetSymbolAddress((void**)&pdl, g_dl);
    cudaGetSymbolAddress((void**)&psh, g_sh);
    cudaGetSymbolAddress((void**)&psl, g_sl);

    cudaFuncSetAttribute(hybrid_gemm_kernel, cudaFuncAttributeMaxDynamicSharedMemorySize, TSMEM);

    transpose_kernel<<<dim3(HW_/32, C_/32, B_), dim3(32,8)>>>(img, pft);
    valign_kernel<<<BV_/8, 256>>>(pft, vpos, vpad, px, pxh, pxl);
    zero_deg_kernel<<<(V_+255)/256, 256>>>();
    count_deg_kernel<<<(E_+255)/256, 256>>>(edges);
    scan_kernel<<<1, 1024>>>();
    fill_adj_kernel<<<(E_+255)/256, 256>>>(edges);
    wsplit_all_kernel<<<384, 256>>>(w0_1, w1_1, w0_2, w1_2, w0_3, w1_3, pwh, pwl);

    // conv1: d = g@W0_1 + b0_1 + nsum(g)@W1_1 ; emits fp32 d + (dh,dl)
    nsum_kernel<<<BV_/8, 256>>>(px, psh, psl);
    hybrid_gemm_kernel<<<BV_/128, 256, TSMEM>>>(px, pxh, pxl, psh, psl,
        w0_1, w1_1, pwh + 0*16384, pwl + 0*16384, b0_1, nullptr, pd, pdh, pdl);
    // conv2: t = d@W0_2 + b0_2 + nsum(d)@W1_2 ; emits fp32 t + (xh,xl)
    nsum_kernel<<<BV_/8, 256>>>(pd, psh, psl);
    hybrid_gemm_kernel<<<BV_/128, 256, TSMEM>>>(pd, pdh, pdl, psh, psl,
        w0_2, w1_2, pwh + 2*16384, pwl + 2*16384, b0_2, nullptr, pt, pxh, pxl);
    // conv3 (+ fused final add of d): fp32 out only
    nsum_kernel<<<BV_/8, 256>>>(pt, psh, psl);
    hybrid_gemm_kernel<<<BV_/128, 256, TSMEM>>>(pt, pxh, pxl, psh, psl,
        w0_3, w1_3, pwh + 4*16384, pwl + 4*16384, b0_3, pd, out, nullptr, nullptr);
}